// round 1
// baseline (speedup 1.0000x reference)
#include <cuda_runtime.h>
#include <cstdint>

#define B_  2
#define S_  2048
#define DIM_ 2048
#define NH_ 16
#define HD_ 128
#define MROWS (B_*S_)          // 4096
#define NSPLIT 16

// ---------------- scratch (device globals; no allocation) ----------------
__device__ float g_Q[(size_t)MROWS * DIM_];
__device__ float g_K[(size_t)MROWS * DIM_];
__device__ float g_V[(size_t)MROWS * DIM_];
__device__ float g_A[(size_t)MROWS * DIM_];
__device__ float g_Mp[(size_t)NSPLIT * B_ * NH_ * HD_ * HD_]; // partials
__device__ float g_M [(size_t)B_ * NH_ * HD_ * HD_];

// ---------------- generic SGEMM: C[m,n] = sum_k A[m,k]*B[n,k] + bias[n] ---
// 128x128 block tile, BK=16, 256 threads, 8x8 per thread, warp-tiled.
__global__ void __launch_bounds__(256)
gemm_nt_bias(const float* __restrict__ A, const float* __restrict__ B,
             const float* __restrict__ bias, float* __restrict__ C,
             int M, int N, int K)
{
    __shared__ float As[16][132];
    __shared__ float Bs[16][132];

    const int tid = threadIdx.x;
    const int bx = blockIdx.x;   // N tile
    const int by = blockIdx.y;   // M tile

    // load mapping: each thread loads 2 float4 per matrix per K-chunk
    const int lr = tid >> 1;           // 0..127 row within tile
    const int lk = (tid & 1) * 4;      // 0 or 4
    const float* Ap = A + (size_t)(by * 128 + lr) * K + lk;
    const float* Bp = B + (size_t)(bx * 128 + lr) * K + lk;

    // compute mapping: warps 4x2, lanes 4x8, 8x8 per thread
    const int lane = tid & 31, w = tid >> 5;
    const int tr = (w & 3) * 32 + (lane >> 3) * 8;   // row offset 0..127
    const int tc = (w >> 2) * 64 + (lane & 7) * 8;   // col offset 0..127

    float acc[8][8];
#pragma unroll
    for (int i = 0; i < 8; i++)
#pragma unroll
        for (int j = 0; j < 8; j++) acc[i][j] = 0.f;

    for (int k0 = 0; k0 < K; k0 += 16) {
        float4 a0 = *(const float4*)(Ap + k0);
        float4 a1 = *(const float4*)(Ap + k0 + 8);
        float4 b0 = *(const float4*)(Bp + k0);
        float4 b1 = *(const float4*)(Bp + k0 + 8);
        As[lk + 0][lr] = a0.x; As[lk + 1][lr] = a0.y;
        As[lk + 2][lr] = a0.z; As[lk + 3][lr] = a0.w;
        As[lk + 8][lr] = a1.x; As[lk + 9][lr] = a1.y;
        As[lk +10][lr] = a1.z; As[lk +11][lr] = a1.w;
        Bs[lk + 0][lr] = b0.x; Bs[lk + 1][lr] = b0.y;
        Bs[lk + 2][lr] = b0.z; Bs[lk + 3][lr] = b0.w;
        Bs[lk + 8][lr] = b1.x; Bs[lk + 9][lr] = b1.y;
        Bs[lk +10][lr] = b1.z; Bs[lk +11][lr] = b1.w;
        __syncthreads();

#pragma unroll
        for (int kk = 0; kk < 16; kk++) {
            float a[8], b[8];
            *(float4*)(a)     = *(const float4*)&As[kk][tr];
            *(float4*)(a + 4) = *(const float4*)&As[kk][tr + 4];
            *(float4*)(b)     = *(const float4*)&Bs[kk][tc];
            *(float4*)(b + 4) = *(const float4*)&Bs[kk][tc + 4];
#pragma unroll
            for (int i = 0; i < 8; i++)
#pragma unroll
                for (int j = 0; j < 8; j++)
                    acc[i][j] += a[i] * b[j];
        }
        __syncthreads();
    }

    float bv[8];
    const float* bp = bias + bx * 128 + tc;
#pragma unroll
    for (int j = 0; j < 8; j++) bv[j] = bp[j];

#pragma unroll
    for (int i = 0; i < 8; i++) {
        float* cp = C + (size_t)(by * 128 + tr + i) * N + bx * 128 + tc;
        float4 o0 = make_float4(acc[i][0] + bv[0], acc[i][1] + bv[1],
                                acc[i][2] + bv[2], acc[i][3] + bv[3]);
        float4 o1 = make_float4(acc[i][4] + bv[4], acc[i][5] + bv[5],
                                acc[i][6] + bv[6], acc[i][7] + bv[7]);
        *(float4*)(cp)     = o0;
        *(float4*)(cp + 4) = o1;
    }
}

// ---------------- RoPE on Q and K in-place --------------------------------
__global__ void rope_kernel(float* __restrict__ Q, float* __restrict__ K,
                            const float* __restrict__ fc,
                            const float* __restrict__ fs)
{
    int idx = blockIdx.x * 256 + threadIdx.x;       // < 4194304
    int i  = idx & 63;
    int h  = (idx >> 6) & 15;
    int bs = idx >> 10;                              // 0..4095
    int s  = bs & (S_ - 1);
    float c  = fc[(s << 6) + i];
    float sn = fs[(s << 6) + i];
    size_t base = ((size_t)bs << 11) + (h << 7) + (i << 1);
    float2 q = *(float2*)(Q + base);
    float2 k = *(float2*)(K + base);
    *(float2*)(Q + base) = make_float2(q.x * c - q.y * sn, q.x * sn + q.y * c);
    *(float2*)(K + base) = make_float2(k.x * c - k.y * sn, k.x * sn + k.y * c);
}

// ---------------- Mp[split,bh,d1,d2] = sum_{s in chunk} K[s,d1]*V[s,d2] ---
__global__ void __launch_bounds__(256)
kv_outer(const float* __restrict__ K, const float* __restrict__ V,
         float* __restrict__ Mp)
{
    const int split = blockIdx.x;     // 0..15
    const int bh    = blockIdx.y;     // 0..31
    const int b = bh >> 4, h = bh & 15;

    __shared__ float Ks[8][128];
    __shared__ float Vs[8][128];

    const int tid = threadIdx.x;
    const int lr = tid >> 5;          // 0..7  (s within chunk)
    const int lc = (tid & 31) * 4;    // 0..124

    const int lane = tid & 31, w = tid >> 5;
    const int tr = (w & 3) * 32 + (lane >> 3) * 8;
    const int tc = (w >> 2) * 64 + (lane & 7) * 8;

    const size_t base = ((size_t)(b * S_ + split * 128 + lr)) * DIM_ + h * HD_ + lc;

    float acc[8][8];
#pragma unroll
    for (int i = 0; i < 8; i++)
#pragma unroll
        for (int j = 0; j < 8; j++) acc[i][j] = 0.f;

    for (int sc = 0; sc < 128; sc += 8) {
        float4 k4 = *(const float4*)(K + base + (size_t)sc * DIM_);
        float4 v4 = *(const float4*)(V + base + (size_t)sc * DIM_);
        *(float4*)&Ks[lr][lc] = k4;
        *(float4*)&Vs[lr][lc] = v4;
        __syncthreads();
#pragma unroll
        for (int ss = 0; ss < 8; ss++) {
            float a[8], bb[8];
            *(float4*)(a)      = *(const float4*)&Ks[ss][tr];
            *(float4*)(a + 4)  = *(const float4*)&Ks[ss][tr + 4];
            *(float4*)(bb)     = *(const float4*)&Vs[ss][tc];
            *(float4*)(bb + 4) = *(const float4*)&Vs[ss][tc + 4];
#pragma unroll
            for (int i = 0; i < 8; i++)
#pragma unroll
                for (int j = 0; j < 8; j++)
                    acc[i][j] += a[i] * bb[j];
        }
        __syncthreads();
    }

    float* out = Mp + (size_t)split * (B_ * NH_ * HD_ * HD_) + (size_t)bh * (HD_ * HD_);
#pragma unroll
    for (int i = 0; i < 8; i++) {
        float* cp = out + (size_t)(tr + i) * HD_ + tc;
        *(float4*)(cp)     = make_float4(acc[i][0], acc[i][1], acc[i][2], acc[i][3]);
        *(float4*)(cp + 4) = make_float4(acc[i][4], acc[i][5], acc[i][6], acc[i][7]);
    }
}

// ---------------- M = (sum_splits Mp) / sqrt(HD) ---------------------------
__global__ void reduce_m(const float* __restrict__ Mp, float* __restrict__ M)
{
    int i = blockIdx.x * 256 + threadIdx.x;          // < 524288
    const int stride = B_ * NH_ * HD_ * HD_;
    float s = 0.f;
#pragma unroll
    for (int p = 0; p < NSPLIT; p++) s += Mp[(size_t)p * stride + i];
    M[i] = s * 0.08838834764831845f;                 // 1/sqrt(128)
}

// ---------------- A[s,d] = sum_{d2} Q[s,d2] * M[d2,d]  per (b,h) ----------
__global__ void __launch_bounds__(256)
attn_qm(const float* __restrict__ Q, const float* __restrict__ M,
        float* __restrict__ Aout)
{
    const int st = blockIdx.x;        // 0..15 s-tile
    const int bh = blockIdx.y;        // 0..31
    const int b = bh >> 4, h = bh & 15;

    __shared__ float Qs[8][132];      // [kk][srow] (transposed)
    __shared__ float Ms[8][128];      // [kk][d]

    const int tid = threadIdx.x;
    const int lr = tid >> 1;          // 0..127 s row
    const int lk = (tid & 1) * 4;     // 0 or 4
    const float* Qbase = Q + ((size_t)(b * S_ + st * 128 + lr)) * DIM_ + h * HD_ + lk;

    const int mr = tid >> 5;          // 0..7
    const int mc = (tid & 31) * 4;

    const int lane = tid & 31, w = tid >> 5;
    const int tr = (w & 3) * 32 + (lane >> 3) * 8;
    const int tc = (w >> 2) * 64 + (lane & 7) * 8;

    float acc[8][8];
#pragma unroll
    for (int i = 0; i < 8; i++)
#pragma unroll
        for (int j = 0; j < 8; j++) acc[i][j] = 0.f;

    const float* Mbh = M + (size_t)bh * (HD_ * HD_);

    for (int k0 = 0; k0 < 128; k0 += 8) {
        float4 q4 = *(const float4*)(Qbase + k0);
        Qs[lk + 0][lr] = q4.x; Qs[lk + 1][lr] = q4.y;
        Qs[lk + 2][lr] = q4.z; Qs[lk + 3][lr] = q4.w;
        float4 m4 = *(const float4*)(Mbh + (size_t)(k0 + mr) * HD_ + mc);
        *(float4*)&Ms[mr][mc] = m4;
        __syncthreads();
#pragma unroll
        for (int kk = 0; kk < 8; kk++) {
            float a[8], bb[8];
            *(float4*)(a)      = *(const float4*)&Qs[kk][tr];
            *(float4*)(a + 4)  = *(const float4*)&Qs[kk][tr + 4];
            *(float4*)(bb)     = *(const float4*)&Ms[kk][tc];
            *(float4*)(bb + 4) = *(const float4*)&Ms[kk][tc + 4];
#pragma unroll
            for (int i = 0; i < 8; i++)
#pragma unroll
                for (int j = 0; j < 8; j++)
                    acc[i][j] += a[i] * bb[j];
        }
        __syncthreads();
    }

#pragma unroll
    for (int i = 0; i < 8; i++) {
        float* cp = Aout + ((size_t)(b * S_ + st * 128 + tr + i)) * DIM_ + h * HD_ + tc;
        *(float4*)(cp)     = make_float4(acc[i][0], acc[i][1], acc[i][2], acc[i][3]);
        *(float4*)(cp + 4) = make_float4(acc[i][4], acc[i][5], acc[i][6], acc[i][7]);
    }
}

// ---------------------------------------------------------------------------
extern "C" void kernel_launch(void* const* d_in, const int* in_sizes, int n_in,
                              void* d_out, int out_size)
{
    const float* x  = (const float*)d_in[0];
    const float* fc = (const float*)d_in[1];
    const float* fs = (const float*)d_in[2];
    const float* wq = (const float*)d_in[3];
    const float* bq = (const float*)d_in[4];
    const float* wk = (const float*)d_in[5];
    const float* bk = (const float*)d_in[6];
    const float* wv = (const float*)d_in[7];
    const float* bv = (const float*)d_in[8];
    const float* wo = (const float*)d_in[9];
    const float* bo = (const float*)d_in[10];
    float* out = (float*)d_out;

    float *pQ, *pK, *pV, *pA, *pMp, *pM;
    cudaGetSymbolAddress((void**)&pQ,  g_Q);
    cudaGetSymbolAddress((void**)&pK,  g_K);
    cudaGetSymbolAddress((void**)&pV,  g_V);
    cudaGetSymbolAddress((void**)&pA,  g_A);
    cudaGetSymbolAddress((void**)&pMp, g_Mp);
    cudaGetSymbolAddress((void**)&pM,  g_M);

    dim3 blk(256);
    dim3 gGemm(DIM_ / 128, MROWS / 128);   // (16, 32)

    gemm_nt_bias<<<gGemm, blk>>>(x, wq, bq, pQ, MROWS, DIM_, DIM_);
    gemm_nt_bias<<<gGemm, blk>>>(x, wk, bk, pK, MROWS, DIM_, DIM_);
    gemm_nt_bias<<<gGemm, blk>>>(x, wv, bv, pV, MROWS, DIM_, DIM_);

    rope_kernel<<<(B_ * S_ * NH_ * (HD_ / 2)) / 256, blk>>>(pQ, pK, fc, fs);

    kv_outer<<<dim3(NSPLIT, B_ * NH_), blk>>>(pK, pV, pMp);
    reduce_m<<<(B_ * NH_ * HD_ * HD_) / 256, blk>>>(pMp, pM);

    attn_qm<<<dim3(S_ / 128, B_ * NH_), blk>>>(pQ, pM, pA);

    gemm_nt_bias<<<gGemm, blk>>>(pA, wo, bo, out, MROWS, DIM_, DIM_);
}

// round 4
// speedup vs baseline: 2.9280x; 2.9280x over previous
#include <cuda_runtime.h>
#include <cuda_bf16.h>
#include <cstdint>

#define B_  2
#define S_  2048
#define DIM_ 2048
#define NH_ 16
#define HD_ 128
#define MROWS (B_*S_)          // 4096
#define NSPLIT 16

// ---------------- scratch (device globals; no allocation) ----------------
__device__ __align__(16) float g_Q[(size_t)MROWS * DIM_];
__device__ __align__(16) float g_K[(size_t)MROWS * DIM_];
__device__ __align__(16) float g_V[(size_t)MROWS * DIM_];
__device__ __align__(16) float g_A[(size_t)MROWS * DIM_];
__device__ __align__(16) float g_Mp[(size_t)NSPLIT * B_ * NH_ * HD_ * HD_];
__device__ __align__(16) float g_M [(size_t)B_ * NH_ * HD_ * HD_];

__device__ __align__(16) __nv_bfloat16 g_xhi[(size_t)MROWS * DIM_];
__device__ __align__(16) __nv_bfloat16 g_xlo[(size_t)MROWS * DIM_];
__device__ __align__(16) __nv_bfloat16 g_ahi[(size_t)MROWS * DIM_];
__device__ __align__(16) __nv_bfloat16 g_alo[(size_t)MROWS * DIM_];
__device__ __align__(16) __nv_bfloat16 g_whi[4][(size_t)DIM_ * DIM_];
__device__ __align__(16) __nv_bfloat16 g_wlo[4][(size_t)DIM_ * DIM_];

// ======================= sm_80-level PTX helpers ==========================
__device__ __forceinline__ uint32_t smem_u32(const void* p) {
    uint32_t a;
    asm("{ .reg .u64 t; cvta.to.shared.u64 t, %1; cvt.u32.u64 %0, t; }"
        : "=r"(a) : "l"(p));
    return a;
}

__device__ __forceinline__ void ldsm_x4(uint32_t* r, uint32_t addr) {
    asm volatile("ldmatrix.sync.aligned.m8n8.x4.shared.b16 {%0,%1,%2,%3}, [%4];"
                 : "=r"(r[0]), "=r"(r[1]), "=r"(r[2]), "=r"(r[3]) : "r"(addr));
}

__device__ __forceinline__ void mma_bf16(float* d, const uint32_t* a, const uint32_t* b) {
    asm volatile(
        "mma.sync.aligned.m16n8k16.row.col.f32.bf16.bf16.f32 "
        "{%0,%1,%2,%3}, {%4,%5,%6,%7}, {%8,%9}, {%0,%1,%2,%3};"
        : "+f"(d[0]), "+f"(d[1]), "+f"(d[2]), "+f"(d[3])
        : "r"(a[0]), "r"(a[1]), "r"(a[2]), "r"(a[3]), "r"(b[0]), "r"(b[1]));
}

#define CP_ASYNC16(dst, src) \
    asm volatile("cp.async.cg.shared.global [%0], [%1], 16;" :: "r"(dst), "l"(src))
#define CP_COMMIT() asm volatile("cp.async.commit_group;" ::: "memory")
#define CP_WAIT0()  asm volatile("cp.async.wait_group 0;" ::: "memory")
#define CP_WAIT1()  asm volatile("cp.async.wait_group 1;" ::: "memory")

#define SW128(bo) ((bo) ^ (((bo) >> 3) & 0x70))

// ============ HMMA GEMM: C[m,n] = sum_k A[m,k]*B[n,k] + bias[n] ============
// fp32 via bf16 hi/lo 3-pass. Tile 128x128, BK=64, 256 threads (8 warps 2Mx4N),
// double-buffered cp.async staging. smem per stage: 4 operands x 16KB.
#define STAGE_BYTES 65536
#define GEMM_SMEM   (2 * STAGE_BYTES)

__global__ void __launch_bounds__(256)
gemm_hmma(const __nv_bfloat16* __restrict__ Ahi, const __nv_bfloat16* __restrict__ Alo,
          const __nv_bfloat16* __restrict__ Bhi, const __nv_bfloat16* __restrict__ Blo,
          const float* __restrict__ bias, float* __restrict__ C,
          int M, int N, int K)
{
    extern __shared__ char smem[];
    const uint32_t sbase = smem_u32(smem);
    const int tid  = threadIdx.x;
    const int lane = tid & 31;
    const int w    = tid >> 5;
    const int wm   = (w & 1) * 64;     // warp M offset within tile
    const int wn   = (w >> 1) * 32;    // warp N offset within tile
    const int row0 = blockIdx.y * 128;
    const int col0 = blockIdx.x * 128;

    const __nv_bfloat16* gb[4] = {
        Ahi + (size_t)row0 * K, Alo + (size_t)row0 * K,
        Bhi + (size_t)col0 * K, Blo + (size_t)col0 * K };

    float acc[4][4][4];
#pragma unroll
    for (int i = 0; i < 4; i++)
#pragma unroll
        for (int j = 0; j < 4; j++)
#pragma unroll
            for (int q = 0; q < 4; q++) acc[i][j][q] = 0.f;

    const int chunks = K >> 6;

    // ---- stage loader (issues 16 cp.async) ----
    auto stage_load = [&](int buf, int kbase) {
        const uint32_t sp0 = sbase + buf * STAGE_BYTES;
#pragma unroll
        for (int m = 0; m < 4; m++) {
            const __nv_bfloat16* gp = gb[m] + kbase;
            const uint32_t sp = sp0 + m * 16384;
#pragma unroll
            for (int j = 0; j < 4; j++) {
                int id  = j * 256 + tid;
                int row = id >> 3;
                int ch  = id & 7;
                uint32_t bo = row * 128 + ch * 16;
                CP_ASYNC16(sp + SW128(bo), (const char*)(gp + (size_t)row * K) + ch * 16);
            }
        }
    };

    stage_load(0, 0);
    CP_COMMIT();

    // precompute lane pieces for ldmatrix addressing
    const int a_row  = lane & 15;          // row within 16
    const int a_koff = (lane >> 4) * 16;   // byte offset within 32B k-span
    const int b_row  = (lane & 7) + ((lane >> 4) << 3);  // n row within 16
    const int b_koff = ((lane >> 3) & 1) * 16;

    for (int c = 0; c < chunks; c++) {
        if (c + 1 < chunks) {
            stage_load((c + 1) & 1, (c + 1) * 64);
            CP_COMMIT();
            CP_WAIT1();
        } else {
            CP_WAIT0();
        }
        __syncthreads();

        const uint32_t sA_hi = sbase + (c & 1) * STAGE_BYTES;
        const uint32_t sA_lo = sA_hi + 16384;
        const uint32_t sB_hi = sA_hi + 32768;
        const uint32_t sB_lo = sA_hi + 49152;

#pragma unroll
        for (int ks = 0; ks < 4; ks++) {
            const int kb2 = ks * 32;   // byte offset of k16 step
            uint32_t ahi[4][4], alo[4][4], bhi[2][4], blo[2][4];
#pragma unroll
            for (int mt = 0; mt < 4; mt++) {
                uint32_t bo = (wm + mt * 16 + a_row) * 128 + kb2 + a_koff;
                uint32_t sw = SW128(bo);
                ldsm_x4(ahi[mt], sA_hi + sw);
                ldsm_x4(alo[mt], sA_lo + sw);
            }
#pragma unroll
            for (int bt = 0; bt < 2; bt++) {
                uint32_t bo = (wn + bt * 16 + b_row) * 128 + kb2 + b_koff;
                uint32_t sw = SW128(bo);
                ldsm_x4(bhi[bt], sB_hi + sw);
                ldsm_x4(blo[bt], sB_lo + sw);
            }
#pragma unroll
            for (int mt = 0; mt < 4; mt++) {
#pragma unroll
                for (int nt = 0; nt < 4; nt++) {
                    const uint32_t* bh = &bhi[nt >> 1][(nt & 1) * 2];
                    const uint32_t* bl = &blo[nt >> 1][(nt & 1) * 2];
                    mma_bf16(acc[mt][nt], ahi[mt], bh);
                    mma_bf16(acc[mt][nt], ahi[mt], bl);
                    mma_bf16(acc[mt][nt], alo[mt], bh);
                }
            }
        }
        __syncthreads();
    }

    // ---- epilogue ----
    const int l4 = lane >> 2;
    const int l2 = (lane & 3) * 2;
#pragma unroll
    for (int mt = 0; mt < 4; mt++) {
#pragma unroll
        for (int nt = 0; nt < 4; nt++) {
            int grow = row0 + wm + mt * 16 + l4;
            int gcol = col0 + wn + nt * 8 + l2;
            float b0 = __ldg(bias + gcol);
            float b1 = __ldg(bias + gcol + 1);
            float* cp0 = C + (size_t)grow * N + gcol;
            float* cp1 = cp0 + 8 * (size_t)N;
            *(float2*)cp0 = make_float2(acc[mt][nt][0] + b0, acc[mt][nt][1] + b1);
            *(float2*)cp1 = make_float2(acc[mt][nt][2] + b0, acc[mt][nt][3] + b1);
        }
    }
}

// ---------------- fp32 -> bf16 hi/lo split ---------------------------------
__global__ void split_fp32_bf16(const float* __restrict__ x,
                                __nv_bfloat16* __restrict__ hi,
                                __nv_bfloat16* __restrict__ lo, int n)
{
    int i = (blockIdx.x * 256 + threadIdx.x) * 4;
    if (i >= n) return;
    float4 v = *(const float4*)(x + i);
    __nv_bfloat16 h0 = __float2bfloat16(v.x), h1 = __float2bfloat16(v.y);
    __nv_bfloat16 h2 = __float2bfloat16(v.z), h3 = __float2bfloat16(v.w);
    __nv_bfloat16 l0 = __float2bfloat16(v.x - __bfloat162float(h0));
    __nv_bfloat16 l1 = __float2bfloat16(v.y - __bfloat162float(h1));
    __nv_bfloat16 l2 = __float2bfloat16(v.z - __bfloat162float(h2));
    __nv_bfloat16 l3 = __float2bfloat16(v.w - __bfloat162float(h3));
    ((__nv_bfloat162*)(hi + i))[0] = __halves2bfloat162(h0, h1);
    ((__nv_bfloat162*)(hi + i))[1] = __halves2bfloat162(h2, h3);
    ((__nv_bfloat162*)(lo + i))[0] = __halves2bfloat162(l0, l1);
    ((__nv_bfloat162*)(lo + i))[1] = __halves2bfloat162(l2, l3);
}

// ---------------- RoPE on Q and K in-place --------------------------------
__global__ void rope_kernel(float* __restrict__ Q, float* __restrict__ K,
                            const float* __restrict__ fc,
                            const float* __restrict__ fs)
{
    int idx = blockIdx.x * 256 + threadIdx.x;
    int i  = idx & 63;
    int h  = (idx >> 6) & 15;
    int bs = idx >> 10;
    int s  = bs & (S_ - 1);
    float c  = fc[(s << 6) + i];
    float sn = fs[(s << 6) + i];
    size_t base = ((size_t)bs << 11) + (h << 7) + (i << 1);
    float2 q = *(float2*)(Q + base);
    float2 k = *(float2*)(K + base);
    *(float2*)(Q + base) = make_float2(q.x * c - q.y * sn, q.x * sn + q.y * c);
    *(float2*)(K + base) = make_float2(k.x * c - k.y * sn, k.x * sn + k.y * c);
}

// ---------------- Mp[split,bh,d1,d2] = sum_{s in chunk} K[s,d1]*V[s,d2] ---
__global__ void __launch_bounds__(256)
kv_outer(const float* __restrict__ K, const float* __restrict__ V,
         float* __restrict__ Mp)
{
    const int split = blockIdx.x;
    const int bh    = blockIdx.y;
    const int b = bh >> 4, h = bh & 15;

    __shared__ float Ks[8][128];
    __shared__ float Vs[8][128];

    const int tid = threadIdx.x;
    const int lr = tid >> 5;
    const int lc = (tid & 31) * 4;

    const int lane = tid & 31, w = tid >> 5;
    const int tr = (w & 3) * 32 + (lane >> 3) * 8;
    const int tc = (w >> 2) * 64 + (lane & 7) * 8;

    const size_t base = ((size_t)(b * S_ + split * 128 + lr)) * DIM_ + h * HD_ + lc;

    float acc[8][8];
#pragma unroll
    for (int i = 0; i < 8; i++)
#pragma unroll
        for (int j = 0; j < 8; j++) acc[i][j] = 0.f;

    for (int sc = 0; sc < 128; sc += 8) {
        float4 k4 = *(const float4*)(K + base + (size_t)sc * DIM_);
        float4 v4 = *(const float4*)(V + base + (size_t)sc * DIM_);
        *(float4*)&Ks[lr][lc] = k4;
        *(float4*)&Vs[lr][lc] = v4;
        __syncthreads();
#pragma unroll
        for (int ss = 0; ss < 8; ss++) {
            float a[8], bb[8];
            *(float4*)(a)      = *(const float4*)&Ks[ss][tr];
            *(float4*)(a + 4)  = *(const float4*)&Ks[ss][tr + 4];
            *(float4*)(bb)     = *(const float4*)&Vs[ss][tc];
            *(float4*)(bb + 4) = *(const float4*)&Vs[ss][tc + 4];
#pragma unroll
            for (int i = 0; i < 8; i++)
#pragma unroll
                for (int j = 0; j < 8; j++)
                    acc[i][j] += a[i] * bb[j];
        }
        __syncthreads();
    }

    float* out = Mp + (size_t)split * (B_ * NH_ * HD_ * HD_) + (size_t)bh * (HD_ * HD_);
#pragma unroll
    for (int i = 0; i < 8; i++) {
        float* cp = out + (size_t)(tr + i) * HD_ + tc;
        *(float4*)(cp)     = make_float4(acc[i][0], acc[i][1], acc[i][2], acc[i][3]);
        *(float4*)(cp + 4) = make_float4(acc[i][4], acc[i][5], acc[i][6], acc[i][7]);
    }
}

// ---------------- M = (sum_splits Mp) / sqrt(HD) ---------------------------
__global__ void reduce_m(const float* __restrict__ Mp, float* __restrict__ M)
{
    int i = blockIdx.x * 256 + threadIdx.x;
    const int stride = B_ * NH_ * HD_ * HD_;
    float s = 0.f;
#pragma unroll
    for (int p = 0; p < NSPLIT; p++) s += Mp[(size_t)p * stride + i];
    M[i] = s * 0.08838834764831845f;
}

// ---------------- A[s,d] = sum_{d2} Q[s,d2] * M[d2,d]  per (b,h) ----------
__global__ void __launch_bounds__(256)
attn_qm(const float* __restrict__ Q, const float* __restrict__ M,
        float* __restrict__ Aout)
{
    const int st = blockIdx.x;
    const int bh = blockIdx.y;
    const int b = bh >> 4, h = bh & 15;

    __shared__ float Qs[8][132];
    __shared__ float Ms[8][128];

    const int tid = threadIdx.x;
    const int lr = tid >> 1;
    const int lk = (tid & 1) * 4;
    const float* Qbase = Q + ((size_t)(b * S_ + st * 128 + lr)) * DIM_ + h * HD_ + lk;

    const int mr = tid >> 5;
    const int mc = (tid & 31) * 4;

    const int lane = tid & 31, w = tid >> 5;
    const int tr = (w & 3) * 32 + (lane >> 3) * 8;
    const int tc = (w >> 2) * 64 + (lane & 7) * 8;

    float acc[8][8];
#pragma unroll
    for (int i = 0; i < 8; i++)
#pragma unroll
        for (int j = 0; j < 8; j++) acc[i][j] = 0.f;

    const float* Mbh = M + (size_t)bh * (HD_ * HD_);

    for (int k0 = 0; k0 < 128; k0 += 8) {
        float4 q4 = *(const float4*)(Qbase + k0);
        Qs[lk + 0][lr] = q4.x; Qs[lk + 1][lr] = q4.y;
        Qs[lk + 2][lr] = q4.z; Qs[lk + 3][lr] = q4.w;
        float4 m4 = *(const float4*)(Mbh + (size_t)(k0 + mr) * HD_ + mc);
        *(float4*)&Ms[mr][mc] = m4;
        __syncthreads();
#pragma unroll
        for (int kk = 0; kk < 8; kk++) {
            float a[8], bb[8];
            *(float4*)(a)      = *(const float4*)&Qs[kk][tr];
            *(float4*)(a + 4)  = *(const float4*)&Qs[kk][tr + 4];
            *(float4*)(bb)     = *(const float4*)&Ms[kk][tc];
            *(float4*)(bb + 4) = *(const float4*)&Ms[kk][tc + 4];
#pragma unroll
            for (int i = 0; i < 8; i++)
#pragma unroll
                for (int j = 0; j < 8; j++)
                    acc[i][j] += a[i] * bb[j];
        }
        __syncthreads();
    }

#pragma unroll
    for (int i = 0; i < 8; i++) {
        float* cp = Aout + ((size_t)(b * S_ + st * 128 + tr + i)) * DIM_ + h * HD_ + tc;
        *(float4*)(cp)     = make_float4(acc[i][0], acc[i][1], acc[i][2], acc[i][3]);
        *(float4*)(cp + 4) = make_float4(acc[i][4], acc[i][5], acc[i][6], acc[i][7]);
    }
}

// ---------------------------------------------------------------------------
extern "C" void kernel_launch(void* const* d_in, const int* in_sizes, int n_in,
                              void* d_out, int out_size)
{
    const float* x  = (const float*)d_in[0];
    const float* fc = (const float*)d_in[1];
    const float* fs = (const float*)d_in[2];
    const float* wq = (const float*)d_in[3];
    const float* bq = (const float*)d_in[4];
    const float* wk = (const float*)d_in[5];
    const float* bk = (const float*)d_in[6];
    const float* wv = (const float*)d_in[7];
    const float* bv = (const float*)d_in[8];
    const float* wo = (const float*)d_in[9];
    const float* bo = (const float*)d_in[10];
    float* out = (float*)d_out;

    float *pQ, *pK, *pV, *pA, *pMp, *pM;
    __nv_bfloat16 *pxh, *pxl, *pah, *pal, *pwh, *pwl;
    cudaGetSymbolAddress((void**)&pQ,  g_Q);
    cudaGetSymbolAddress((void**)&pK,  g_K);
    cudaGetSymbolAddress((void**)&pV,  g_V);
    cudaGetSymbolAddress((void**)&pA,  g_A);
    cudaGetSymbolAddress((void**)&pMp, g_Mp);
    cudaGetSymbolAddress((void**)&pM,  g_M);
    cudaGetSymbolAddress((void**)&pxh, g_xhi);
    cudaGetSymbolAddress((void**)&pxl, g_xlo);
    cudaGetSymbolAddress((void**)&pah, g_ahi);
    cudaGetSymbolAddress((void**)&pal, g_alo);
    cudaGetSymbolAddress((void**)&pwh, g_whi);
    cudaGetSymbolAddress((void**)&pwl, g_wlo);

    cudaFuncSetAttribute(gemm_hmma, cudaFuncAttributeMaxDynamicSharedMemorySize,
                         GEMM_SMEM);

    dim3 blk(256);
    const int NX = MROWS * DIM_;
    const int NW = DIM_ * DIM_;
    const size_t WSTRIDE = (size_t)DIM_ * DIM_;

    split_fp32_bf16<<<NX / 1024, blk>>>(x, pxh, pxl, NX);
    split_fp32_bf16<<<NW / 1024, blk>>>(wq, pwh + 0 * WSTRIDE, pwl + 0 * WSTRIDE, NW);
    split_fp32_bf16<<<NW / 1024, blk>>>(wk, pwh + 1 * WSTRIDE, pwl + 1 * WSTRIDE, NW);
    split_fp32_bf16<<<NW / 1024, blk>>>(wv, pwh + 2 * WSTRIDE, pwl + 2 * WSTRIDE, NW);
    split_fp32_bf16<<<NW / 1024, blk>>>(wo, pwh + 3 * WSTRIDE, pwl + 3 * WSTRIDE, NW);

    dim3 gGemm(DIM_ / 128, MROWS / 128);   // (16, 32)

    gemm_hmma<<<gGemm, blk, GEMM_SMEM>>>(pxh, pxl, pwh + 0 * WSTRIDE, pwl + 0 * WSTRIDE,
                                         bq, pQ, MROWS, DIM_, DIM_);
    gemm_hmma<<<gGemm, blk, GEMM_SMEM>>>(pxh, pxl, pwh + 1 * WSTRIDE, pwl + 1 * WSTRIDE,
                                         bk, pK, MROWS, DIM_, DIM_);
    gemm_hmma<<<gGemm, blk, GEMM_SMEM>>>(pxh, pxl, pwh + 2 * WSTRIDE, pwl + 2 * WSTRIDE,
                                         bv, pV, MROWS, DIM_, DIM_);

    rope_kernel<<<(B_ * S_ * NH_ * (HD_ / 2)) / 256, blk>>>(pQ, pK, fc, fs);

    kv_outer<<<dim3(NSPLIT, B_ * NH_), blk>>>(pK, pV, pMp);
    reduce_m<<<(B_ * NH_ * HD_ * HD_) / 256, blk>>>(pMp, pM);
    attn_qm<<<dim3(S_ / 128, B_ * NH_), blk>>>(pQ, pM, pA);

    split_fp32_bf16<<<NX / 1024, blk>>>(pA, pah, pal, NX);
    gemm_hmma<<<gGemm, blk, GEMM_SMEM>>>(pah, pal, pwh + 3 * WSTRIDE, pwl + 3 * WSTRIDE,
                                         bo, out, MROWS, DIM_, DIM_);
}

// round 5
// speedup vs baseline: 3.1126x; 1.0630x over previous
#include <cuda_runtime.h>
#include <cuda_bf16.h>
#include <cstdint>

#define B_  2
#define S_  2048
#define DIM_ 2048
#define NH_ 16
#define HD_ 128
#define MROWS (B_*S_)          // 4096
#define KVSPLIT 8

// ---------------- scratch (device globals; no allocation) ----------------
__device__ __align__(16) float g_Q[(size_t)MROWS * DIM_];
__device__ __align__(16) float g_K[(size_t)MROWS * DIM_];
__device__ __align__(16) float g_V[(size_t)MROWS * DIM_];
__device__ __align__(16) float g_Mp[(size_t)KVSPLIT * B_ * NH_ * HD_ * HD_];

__device__ __align__(16) __nv_bfloat16 g_xhi[(size_t)MROWS * DIM_];
__device__ __align__(16) __nv_bfloat16 g_xlo[(size_t)MROWS * DIM_];
__device__ __align__(16) __nv_bfloat16 g_whi[4][(size_t)DIM_ * DIM_];
__device__ __align__(16) __nv_bfloat16 g_wlo[4][(size_t)DIM_ * DIM_];

__device__ __align__(16) __nv_bfloat16 g_qhi[(size_t)MROWS * DIM_];
__device__ __align__(16) __nv_bfloat16 g_qlo[(size_t)MROWS * DIM_];
__device__ __align__(16) __nv_bfloat16 g_kthi[(size_t)B_ * NH_ * HD_ * S_];
__device__ __align__(16) __nv_bfloat16 g_ktlo[(size_t)B_ * NH_ * HD_ * S_];
__device__ __align__(16) __nv_bfloat16 g_vthi[(size_t)B_ * NH_ * HD_ * S_];
__device__ __align__(16) __nv_bfloat16 g_vtlo[(size_t)B_ * NH_ * HD_ * S_];
__device__ __align__(16) __nv_bfloat16 g_mthi[(size_t)B_ * NH_ * HD_ * HD_];
__device__ __align__(16) __nv_bfloat16 g_mtlo[(size_t)B_ * NH_ * HD_ * HD_];
__device__ __align__(16) __nv_bfloat16 g_ahi[(size_t)MROWS * DIM_];
__device__ __align__(16) __nv_bfloat16 g_alo[(size_t)MROWS * DIM_];

// ======================= PTX helpers ==========================
__device__ __forceinline__ uint32_t smem_u32(const void* p) {
    uint32_t a;
    asm("{ .reg .u64 t; cvta.to.shared.u64 t, %1; cvt.u32.u64 %0, t; }"
        : "=r"(a) : "l"(p));
    return a;
}

__device__ __forceinline__ void ldsm_x4(uint32_t* r, uint32_t addr) {
    asm volatile("ldmatrix.sync.aligned.m8n8.x4.shared.b16 {%0,%1,%2,%3}, [%4];"
                 : "=r"(r[0]), "=r"(r[1]), "=r"(r[2]), "=r"(r[3]) : "r"(addr));
}

__device__ __forceinline__ void mma_bf16(float* d, const uint32_t* a, const uint32_t* b) {
    asm volatile(
        "mma.sync.aligned.m16n8k16.row.col.f32.bf16.bf16.f32 "
        "{%0,%1,%2,%3}, {%4,%5,%6,%7}, {%8,%9}, {%0,%1,%2,%3};"
        : "+f"(d[0]), "+f"(d[1]), "+f"(d[2]), "+f"(d[3])
        : "r"(a[0]), "r"(a[1]), "r"(a[2]), "r"(a[3]), "r"(b[0]), "r"(b[1]));
}

#define CP_ASYNC16(dst, src) \
    asm volatile("cp.async.cg.shared.global [%0], [%1], 16;" :: "r"(dst), "l"(src))
#define CP_COMMIT() asm volatile("cp.async.commit_group;" ::: "memory")
#define CP_WAIT0()  asm volatile("cp.async.wait_group 0;" ::: "memory")
#define CP_WAIT1()  asm volatile("cp.async.wait_group 1;" ::: "memory")

#define SW128(bo) ((bo) ^ (((bo) >> 3) & 0x70))

__device__ __forceinline__ void split2(float a, float b,
                                       __nv_bfloat162& hi, __nv_bfloat162& lo) {
    __nv_bfloat16 ha = __float2bfloat16(a), hb = __float2bfloat16(b);
    hi = __halves2bfloat162(ha, hb);
    lo = __halves2bfloat162(__float2bfloat16(a - __bfloat162float(ha)),
                            __float2bfloat16(b - __bfloat162float(hb)));
}

// ============ shared 128x128 3-pass bf16 MMA mainloop =====================
#define STAGE_BYTES 65536
#define GEMM_SMEM   (2 * STAGE_BYTES)

__device__ __forceinline__ void mm_tile(
    const __nv_bfloat16* Ahi, const __nv_bfloat16* Alo,
    const __nv_bfloat16* Bhi, const __nv_bfloat16* Blo,
    int lda, int ldb, int chunks, char* smem, float (&acc)[4][4][4])
{
    const uint32_t sbase = smem_u32(smem);
    const int tid  = threadIdx.x;
    const int lane = tid & 31;
    const int w    = tid >> 5;
    const int wm   = (w & 1) * 64;
    const int wn   = (w >> 1) * 32;

    const __nv_bfloat16* gb[4] = {Ahi, Alo, Bhi, Blo};
    const int lds[4] = {lda, lda, ldb, ldb};

    auto stage_load = [&](int buf, int kbase) {
        const uint32_t sp0 = sbase + buf * STAGE_BYTES;
#pragma unroll
        for (int m = 0; m < 4; m++) {
            const __nv_bfloat16* gp = gb[m] + kbase;
            const int ld = lds[m];
            const uint32_t sp = sp0 + m * 16384;
#pragma unroll
            for (int j = 0; j < 4; j++) {
                int id  = j * 256 + tid;
                int row = id >> 3;
                int ch  = id & 7;
                uint32_t bo = row * 128 + ch * 16;
                CP_ASYNC16(sp + SW128(bo), (const char*)(gp + (size_t)row * ld) + ch * 16);
            }
        }
    };

    stage_load(0, 0);
    CP_COMMIT();

    const int a_row  = lane & 15;
    const int a_koff = (lane >> 4) * 16;
    const int b_row  = (lane & 7) + ((lane >> 4) << 3);
    const int b_koff = ((lane >> 3) & 1) * 16;

    for (int c = 0; c < chunks; c++) {
        if (c + 1 < chunks) {
            stage_load((c + 1) & 1, (c + 1) * 64);
            CP_COMMIT();
            CP_WAIT1();
        } else {
            CP_WAIT0();
        }
        __syncthreads();

        const uint32_t sA_hi = sbase + (c & 1) * STAGE_BYTES;
        const uint32_t sA_lo = sA_hi + 16384;
        const uint32_t sB_hi = sA_hi + 32768;
        const uint32_t sB_lo = sA_hi + 49152;

#pragma unroll
        for (int ks = 0; ks < 4; ks++) {
            const int kb2 = ks * 32;
            uint32_t ahi[4][4], alo[4][4], bhi[2][4], blo[2][4];
#pragma unroll
            for (int mt = 0; mt < 4; mt++) {
                uint32_t bo = (wm + mt * 16 + a_row) * 128 + kb2 + a_koff;
                uint32_t sw = SW128(bo);
                ldsm_x4(ahi[mt], sA_hi + sw);
                ldsm_x4(alo[mt], sA_lo + sw);
            }
#pragma unroll
            for (int bt = 0; bt < 2; bt++) {
                uint32_t bo = (wn + bt * 16 + b_row) * 128 + kb2 + b_koff;
                uint32_t sw = SW128(bo);
                ldsm_x4(bhi[bt], sB_hi + sw);
                ldsm_x4(blo[bt], sB_lo + sw);
            }
#pragma unroll
            for (int mt = 0; mt < 4; mt++) {
#pragma unroll
                for (int nt = 0; nt < 4; nt++) {
                    const uint32_t* bh = &bhi[nt >> 1][(nt & 1) * 2];
                    const uint32_t* bl = &blo[nt >> 1][(nt & 1) * 2];
                    mma_bf16(acc[mt][nt], ahi[mt], bh);
                    mma_bf16(acc[mt][nt], ahi[mt], bl);
                    mma_bf16(acc[mt][nt], alo[mt], bh);
                }
            }
        }
        __syncthreads();
    }
}

#define ACC_INIT(acc) \
    _Pragma("unroll") for (int i = 0; i < 4; i++) \
    _Pragma("unroll") for (int j = 0; j < 4; j++) \
    _Pragma("unroll") for (int q = 0; q < 4; q++) acc[i][j][q] = 0.f;

// ============ fused QKV GEMM: grid (48, 32) ================================
__global__ void __launch_bounds__(256)
gemm_qkv(const __nv_bfloat16* __restrict__ xhi, const __nv_bfloat16* __restrict__ xlo,
         const __nv_bfloat16* __restrict__ whi, const __nv_bfloat16* __restrict__ wlo,
         const float* __restrict__ bq, const float* __restrict__ bk,
         const float* __restrict__ bv,
         float* __restrict__ pQ, float* __restrict__ pK, float* __restrict__ pV)
{
    extern __shared__ char smem[];
    const int bx = blockIdx.x, by = blockIdx.y;
    const int wsel = bx >> 4;
    const int col0 = (bx & 15) * 128;
    const int row0 = by * 128;
    const float* bias = (wsel == 0) ? bq : ((wsel == 1) ? bk : bv);
    float* C = (wsel == 0) ? pQ : ((wsel == 1) ? pK : pV);

    float acc[4][4][4];
    ACC_INIT(acc)
    mm_tile(xhi + (size_t)row0 * DIM_, xlo + (size_t)row0 * DIM_,
            whi + (size_t)bx * 128 * DIM_, wlo + (size_t)bx * 128 * DIM_,
            DIM_, DIM_, DIM_ / 64, smem, acc);

    const int lane = threadIdx.x & 31, w = threadIdx.x >> 5;
    const int wm = (w & 1) * 64, wn = (w >> 1) * 32;
    const int l4 = lane >> 2, l2 = (lane & 3) * 2;
#pragma unroll
    for (int mt = 0; mt < 4; mt++) {
#pragma unroll
        for (int nt = 0; nt < 4; nt++) {
            int grow = row0 + wm + mt * 16 + l4;
            int gcol = col0 + wn + nt * 8 + l2;
            float b0 = __ldg(bias + gcol);
            float b1 = __ldg(bias + gcol + 1);
            float* cp0 = C + (size_t)grow * DIM_ + gcol;
            float* cp1 = cp0 + 8 * (size_t)DIM_;
            *(float2*)cp0 = make_float2(acc[mt][nt][0] + b0, acc[mt][nt][1] + b1);
            *(float2*)cp1 = make_float2(acc[mt][nt][2] + b0, acc[mt][nt][3] + b1);
        }
    }
}

// ============ WO GEMM: grid (16, 32) =======================================
__global__ void __launch_bounds__(256)
gemm_wo(const __nv_bfloat16* __restrict__ Ahi, const __nv_bfloat16* __restrict__ Alo,
        const __nv_bfloat16* __restrict__ Bhi, const __nv_bfloat16* __restrict__ Blo,
        const float* __restrict__ bias, float* __restrict__ C)
{
    extern __shared__ char smem[];
    const int row0 = blockIdx.y * 128;
    const int col0 = blockIdx.x * 128;

    float acc[4][4][4];
    ACC_INIT(acc)
    mm_tile(Ahi + (size_t)row0 * DIM_, Alo + (size_t)row0 * DIM_,
            Bhi + (size_t)col0 * DIM_, Blo + (size_t)col0 * DIM_,
            DIM_, DIM_, DIM_ / 64, smem, acc);

    const int lane = threadIdx.x & 31, w = threadIdx.x >> 5;
    const int wm = (w & 1) * 64, wn = (w >> 1) * 32;
    const int l4 = lane >> 2, l2 = (lane & 3) * 2;
#pragma unroll
    for (int mt = 0; mt < 4; mt++) {
#pragma unroll
        for (int nt = 0; nt < 4; nt++) {
            int grow = row0 + wm + mt * 16 + l4;
            int gcol = col0 + wn + nt * 8 + l2;
            float b0 = __ldg(bias + gcol);
            float b1 = __ldg(bias + gcol + 1);
            float* cp0 = C + (size_t)grow * DIM_ + gcol;
            float* cp1 = cp0 + 8 * (size_t)DIM_;
            *(float2*)cp0 = make_float2(acc[mt][nt][0] + b0, acc[mt][nt][1] + b1);
            *(float2*)cp1 = make_float2(acc[mt][nt][2] + b0, acc[mt][nt][3] + b1);
        }
    }
}

// ============ KtV GEMM: Mp[ks][bh] = Kt[bh] chunk . Vt[bh] chunk ===========
// grid (KVSPLIT, 32). A rows d2 (k=s), B rows d (k=s), K=256.
__global__ void __launch_bounds__(256)
kv_hmma(const __nv_bfloat16* __restrict__ kthi, const __nv_bfloat16* __restrict__ ktlo,
        const __nv_bfloat16* __restrict__ vthi, const __nv_bfloat16* __restrict__ vtlo,
        float* __restrict__ Mp)
{
    extern __shared__ char smem[];
    const int ksp = blockIdx.x;
    const int bh  = blockIdx.y;
    const size_t base = (size_t)bh * HD_ * S_ + ksp * (S_ / KVSPLIT);

    float acc[4][4][4];
    ACC_INIT(acc)
    mm_tile(kthi + base, ktlo + base, vthi + base, vtlo + base,
            S_, S_, (S_ / KVSPLIT) / 64, smem, acc);

    float* C = Mp + ((size_t)ksp * 32 + bh) * (HD_ * HD_);
    const int lane = threadIdx.x & 31, w = threadIdx.x >> 5;
    const int wm = (w & 1) * 64, wn = (w >> 1) * 32;
    const int l4 = lane >> 2, l2 = (lane & 3) * 2;
#pragma unroll
    for (int mt = 0; mt < 4; mt++) {
#pragma unroll
        for (int nt = 0; nt < 4; nt++) {
            int grow = wm + mt * 16 + l4;
            int gcol = wn + nt * 8 + l2;
            float* cp0 = C + (size_t)grow * HD_ + gcol;
            float* cp1 = cp0 + 8 * HD_;
            *(float2*)cp0 = make_float2(acc[mt][nt][0], acc[mt][nt][1]);
            *(float2*)cp1 = make_float2(acc[mt][nt][2], acc[mt][nt][3]);
        }
    }
}

// ============ attn GEMM: A[s,d] = Q[s,:].Mt[d,:] per bh; grid (16,32) ======
__global__ void __launch_bounds__(256)
attn_hmma(const __nv_bfloat16* __restrict__ qhi, const __nv_bfloat16* __restrict__ qlo,
          const __nv_bfloat16* __restrict__ mthi, const __nv_bfloat16* __restrict__ mtlo,
          __nv_bfloat16* __restrict__ ahi, __nv_bfloat16* __restrict__ alo)
{
    extern __shared__ char smem[];
    const int st = blockIdx.x;
    const int bh = blockIdx.y;
    const int b = bh >> 4, h = bh & 15;
    const size_t abase = ((size_t)(b * S_ + st * 128)) * DIM_ + h * HD_;
    const size_t mbase = (size_t)bh * HD_ * HD_;

    float acc[4][4][4];
    ACC_INIT(acc)
    mm_tile(qhi + abase, qlo + abase, mthi + mbase, mtlo + mbase,
            DIM_, HD_, HD_ / 64, smem, acc);

    const int lane = threadIdx.x & 31, w = threadIdx.x >> 5;
    const int wm = (w & 1) * 64, wn = (w >> 1) * 32;
    const int l4 = lane >> 2, l2 = (lane & 3) * 2;
#pragma unroll
    for (int mt = 0; mt < 4; mt++) {
#pragma unroll
        for (int nt = 0; nt < 4; nt++) {
            size_t off0 = abase + (size_t)(wm + mt * 16 + l4) * DIM_ + wn + nt * 8 + l2;
            size_t off1 = off0 + 8 * (size_t)DIM_;
            __nv_bfloat162 hi, lo;
            split2(acc[mt][nt][0], acc[mt][nt][1], hi, lo);
            *(__nv_bfloat162*)(ahi + off0) = hi;
            *(__nv_bfloat162*)(alo + off0) = lo;
            split2(acc[mt][nt][2], acc[mt][nt][3], hi, lo);
            *(__nv_bfloat162*)(ahi + off1) = hi;
            *(__nv_bfloat162*)(alo + off1) = lo;
        }
    }
}

// ============ prep: rope+split Q (row), rope+transpose-split K, ============
// ============       transpose-split V. grid (16, 32), 256 thr. ============
#define PREP_SMEM (2 * 128 * 132 * 2)

__global__ void __launch_bounds__(256)
prep_qkv(const float* __restrict__ Q, const float* __restrict__ K,
         const float* __restrict__ V,
         const float* __restrict__ fc, const float* __restrict__ fs,
         __nv_bfloat16* __restrict__ qhi, __nv_bfloat16* __restrict__ qlo,
         __nv_bfloat16* __restrict__ kthi, __nv_bfloat16* __restrict__ ktlo,
         __nv_bfloat16* __restrict__ vthi, __nv_bfloat16* __restrict__ vtlo)
{
    extern __shared__ __nv_bfloat16 sm[];
    __nv_bfloat16* shi = sm;
    __nv_bfloat16* slo = sm + 128 * 132;

    const int st = blockIdx.x;
    const int bh = blockIdx.y;
    const int b = bh >> 4, h = bh & 15;
    const int s0 = st * 128;
    const int tid = threadIdx.x;
    const size_t rowbase = ((size_t)(b * S_ + s0)) * DIM_ + h * HD_;
    const size_t tbase = (size_t)bh * HD_ * S_ + s0;

    // ---- Q: rope + split, row-major ----
    for (int idx = tid; idx < 128 * 64; idx += 256) {
        int sl = idx >> 6, i = idx & 63;
        int sg = s0 + sl;
        float c = fc[sg * 64 + i], sn = fs[sg * 64 + i];
        size_t off = rowbase + (size_t)sl * DIM_ + 2 * i;
        float2 q = *(const float2*)(Q + off);
        float o0 = q.x * c - q.y * sn, o1 = q.x * sn + q.y * c;
        __nv_bfloat162 hi, lo;
        split2(o0, o1, hi, lo);
        *(__nv_bfloat162*)(qhi + off) = hi;
        *(__nv_bfloat162*)(qlo + off) = lo;
    }

    // ---- K: rope + split into smem ----
    for (int idx = tid; idx < 128 * 64; idx += 256) {
        int sl = idx >> 6, i = idx & 63;
        int sg = s0 + sl;
        float c = fc[sg * 64 + i], sn = fs[sg * 64 + i];
        float2 k = *(const float2*)(K + rowbase + (size_t)sl * DIM_ + 2 * i);
        float o0 = k.x * c - k.y * sn, o1 = k.x * sn + k.y * c;
        __nv_bfloat162 hi, lo;
        split2(o0, o1, hi, lo);
        *(__nv_bfloat162*)(shi + sl * 132 + 2 * i) = hi;
        *(__nv_bfloat162*)(slo + sl * 132 + 2 * i) = lo;
    }
    __syncthreads();
    // transposed write: Kt[d][s]
    for (int idx = tid; idx < 128 * 64; idx += 256) {
        int d = idx >> 6;
        int sp = (idx & 63) * 2;
        __nv_bfloat162 vh = __halves2bfloat162(shi[sp * 132 + d], shi[(sp + 1) * 132 + d]);
        __nv_bfloat162 vl = __halves2bfloat162(slo[sp * 132 + d], slo[(sp + 1) * 132 + d]);
        size_t off = tbase + (size_t)d * S_ + sp;
        *(__nv_bfloat162*)(kthi + off) = vh;
        *(__nv_bfloat162*)(ktlo + off) = vl;
    }
    __syncthreads();

    // ---- V: split into smem (no rope) ----
    for (int idx = tid; idx < 128 * 64; idx += 256) {
        int sl = idx >> 6, i = idx & 63;
        float2 v = *(const float2*)(V + rowbase + (size_t)sl * DIM_ + 2 * i);
        __nv_bfloat162 hi, lo;
        split2(v.x, v.y, hi, lo);
        *(__nv_bfloat162*)(shi + sl * 132 + 2 * i) = hi;
        *(__nv_bfloat162*)(slo + sl * 132 + 2 * i) = lo;
    }
    __syncthreads();
    for (int idx = tid; idx < 128 * 64; idx += 256) {
        int d = idx >> 6;
        int sp = (idx & 63) * 2;
        __nv_bfloat162 vh = __halves2bfloat162(shi[sp * 132 + d], shi[(sp + 1) * 132 + d]);
        __nv_bfloat162 vl = __halves2bfloat162(slo[sp * 132 + d], slo[(sp + 1) * 132 + d]);
        size_t off = tbase + (size_t)d * S_ + sp;
        *(__nv_bfloat162*)(vthi + off) = vh;
        *(__nv_bfloat162*)(vtlo + off) = vl;
    }
}

// ============ reduce Mp over splits, scale, transpose, split ===============
__global__ void reduce_mt(const float* __restrict__ Mp,
                          __nv_bfloat16* __restrict__ mthi,
                          __nv_bfloat16* __restrict__ mtlo)
{
    int o = blockIdx.x * 256 + threadIdx.x;        // < 32*16384/2 (2 elems each)
    int bh = o >> 13;
    int r  = o & 8191;
    int d  = r >> 6;
    int d2p = (r & 63) * 2;                        // pair of d2
    const float* src = Mp + (size_t)bh * (HD_ * HD_) + (size_t)d2p * HD_ + d;
    float s0 = 0.f, s1 = 0.f;
    const size_t stride = (size_t)32 * HD_ * HD_;
#pragma unroll
    for (int p = 0; p < KVSPLIT; p++) {
        s0 += src[p * stride];
        s1 += src[p * stride + HD_];
    }
    s0 *= 0.08838834764831845f;
    s1 *= 0.08838834764831845f;
    __nv_bfloat162 hi, lo;
    split2(s0, s1, hi, lo);
    size_t off = (size_t)bh * (HD_ * HD_) + (size_t)d * HD_ + d2p;
    *(__nv_bfloat162*)(mthi + off) = hi;
    *(__nv_bfloat162*)(mtlo + off) = lo;
}

// ---------------- fp32 -> bf16 hi/lo split ---------------------------------
__global__ void split_fp32_bf16(const float* __restrict__ x,
                                __nv_bfloat16* __restrict__ hi,
                                __nv_bfloat16* __restrict__ lo, int n)
{
    int i = (blockIdx.x * 256 + threadIdx.x) * 4;
    if (i >= n) return;
    float4 v = *(const float4*)(x + i);
    __nv_bfloat162 h01, l01, h23, l23;
    split2(v.x, v.y, h01, l01);
    split2(v.z, v.w, h23, l23);
    ((__nv_bfloat162*)(hi + i))[0] = h01;
    ((__nv_bfloat162*)(hi + i))[1] = h23;
    ((__nv_bfloat162*)(lo + i))[0] = l01;
    ((__nv_bfloat162*)(lo + i))[1] = l23;
}

// ---------------------------------------------------------------------------
extern "C" void kernel_launch(void* const* d_in, const int* in_sizes, int n_in,
                              void* d_out, int out_size)
{
    const float* x  = (const float*)d_in[0];
    const float* fc = (const float*)d_in[1];
    const float* fs = (const float*)d_in[2];
    const float* wq = (const float*)d_in[3];
    const float* bq = (const float*)d_in[4];
    const float* wk = (const float*)d_in[5];
    const float* bk = (const float*)d_in[6];
    const float* wv = (const float*)d_in[7];
    const float* bv = (const float*)d_in[8];
    const float* wo = (const float*)d_in[9];
    const float* bo = (const float*)d_in[10];
    float* out = (float*)d_out;

    float *pQ, *pK, *pV, *pMp;
    __nv_bfloat16 *pxh, *pxl, *pwh, *pwl;
    __nv_bfloat16 *pqh, *pql, *pkth, *pktl, *pvth, *pvtl, *pmth, *pmtl, *pah, *pal;
    cudaGetSymbolAddress((void**)&pQ,  g_Q);
    cudaGetSymbolAddress((void**)&pK,  g_K);
    cudaGetSymbolAddress((void**)&pV,  g_V);
    cudaGetSymbolAddress((void**)&pMp, g_Mp);
    cudaGetSymbolAddress((void**)&pxh, g_xhi);
    cudaGetSymbolAddress((void**)&pxl, g_xlo);
    cudaGetSymbolAddress((void**)&pwh, g_whi);
    cudaGetSymbolAddress((void**)&pwl, g_wlo);
    cudaGetSymbolAddress((void**)&pqh, g_qhi);
    cudaGetSymbolAddress((void**)&pql, g_qlo);
    cudaGetSymbolAddress((void**)&pkth, g_kthi);
    cudaGetSymbolAddress((void**)&pktl, g_ktlo);
    cudaGetSymbolAddress((void**)&pvth, g_vthi);
    cudaGetSymbolAddress((void**)&pvtl, g_vtlo);
    cudaGetSymbolAddress((void**)&pmth, g_mthi);
    cudaGetSymbolAddress((void**)&pmtl, g_mtlo);
    cudaGetSymbolAddress((void**)&pah, g_ahi);
    cudaGetSymbolAddress((void**)&pal, g_alo);

    cudaFuncSetAttribute(gemm_qkv,  cudaFuncAttributeMaxDynamicSharedMemorySize, GEMM_SMEM);
    cudaFuncSetAttribute(gemm_wo,   cudaFuncAttributeMaxDynamicSharedMemorySize, GEMM_SMEM);
    cudaFuncSetAttribute(kv_hmma,   cudaFuncAttributeMaxDynamicSharedMemorySize, GEMM_SMEM);
    cudaFuncSetAttribute(attn_hmma, cudaFuncAttributeMaxDynamicSharedMemorySize, GEMM_SMEM);
    cudaFuncSetAttribute(prep_qkv,  cudaFuncAttributeMaxDynamicSharedMemorySize, PREP_SMEM);

    dim3 blk(256);
    const int NX = MROWS * DIM_;
    const int NW = DIM_ * DIM_;
    const size_t WSTRIDE = (size_t)DIM_ * DIM_;

    split_fp32_bf16<<<NX / 1024, blk>>>(x, pxh, pxl, NX);
    split_fp32_bf16<<<NW / 1024, blk>>>(wq, pwh + 0 * WSTRIDE, pwl + 0 * WSTRIDE, NW);
    split_fp32_bf16<<<NW / 1024, blk>>>(wk, pwh + 1 * WSTRIDE, pwl + 1 * WSTRIDE, NW);
    split_fp32_bf16<<<NW / 1024, blk>>>(wv, pwh + 2 * WSTRIDE, pwl + 2 * WSTRIDE, NW);
    split_fp32_bf16<<<NW / 1024, blk>>>(wo, pwh + 3 * WSTRIDE, pwl + 3 * WSTRIDE, NW);

    gemm_qkv<<<dim3(48, 32), blk, GEMM_SMEM>>>(pxh, pxl, pwh, pwl,
                                               bq, bk, bv, pQ, pK, pV);

    prep_qkv<<<dim3(16, 32), blk, PREP_SMEM>>>(pQ, pK, pV, fc, fs,
                                               pqh, pql, pkth, pktl, pvth, pvtl);

    kv_hmma<<<dim3(KVSPLIT, 32), blk, GEMM_SMEM>>>(pkth, pktl, pvth, pvtl, pMp);

    reduce_mt<<<(32 * HD_ * HD_ / 2) / 256, blk>>>(pMp, pmth, pmtl);

    attn_hmma<<<dim3(16, 32), blk, GEMM_SMEM>>>(pqh, pql, pmth, pmtl, pah, pal);

    gemm_wo<<<dim3(16, 32), blk, GEMM_SMEM>>>(pah, pal,
                                              pwh + 3 * WSTRIDE, pwl + 3 * WSTRIDE,
                                              bo, out);
}

// round 7
// speedup vs baseline: 4.0883x; 1.3135x over previous
#include <cuda_runtime.h>
#include <cuda_bf16.h>
#include <cuda_fp16.h>
#include <cstdint>

#define B_  2
#define S_  2048
#define DIM_ 2048
#define NH_ 16
#define HD_ 128
#define MROWS (B_*S_)          // 4096
#define KVSPLIT 8

// ---------------- scratch (device globals; no allocation) ----------------
__device__ __align__(16) float g_Q[(size_t)MROWS * DIM_];
__device__ __align__(16) float g_K[(size_t)MROWS * DIM_];
__device__ __align__(16) float g_V[(size_t)MROWS * DIM_];
__device__ __align__(16) float g_Mp[(size_t)KVSPLIT * B_ * NH_ * HD_ * HD_];

// fp16 operands for the big GEMMs (2-pass: A split hi/lo, B rounded)
__device__ __align__(16) __half g_xhi[(size_t)MROWS * DIM_];
__device__ __align__(16) __half g_xlo[(size_t)MROWS * DIM_];
__device__ __align__(16) __half g_w[4][(size_t)DIM_ * DIM_];
__device__ __align__(16) __half g_ahi[(size_t)MROWS * DIM_];
__device__ __align__(16) __half g_alo[(size_t)MROWS * DIM_];

// bf16 hi/lo operands for the small attention GEMMs (3-pass)
__device__ __align__(16) __nv_bfloat16 g_qhi[(size_t)MROWS * DIM_];
__device__ __align__(16) __nv_bfloat16 g_qlo[(size_t)MROWS * DIM_];
__device__ __align__(16) __nv_bfloat16 g_kthi[(size_t)B_ * NH_ * HD_ * S_];
__device__ __align__(16) __nv_bfloat16 g_ktlo[(size_t)B_ * NH_ * HD_ * S_];
__device__ __align__(16) __nv_bfloat16 g_vthi[(size_t)B_ * NH_ * HD_ * S_];
__device__ __align__(16) __nv_bfloat16 g_vtlo[(size_t)B_ * NH_ * HD_ * S_];
__device__ __align__(16) __nv_bfloat16 g_mthi[(size_t)B_ * NH_ * HD_ * HD_];
__device__ __align__(16) __nv_bfloat16 g_mtlo[(size_t)B_ * NH_ * HD_ * HD_];

// ======================= PTX helpers ==========================
__device__ __forceinline__ uint32_t smem_u32(const void* p) {
    uint32_t a;
    asm("{ .reg .u64 t; cvta.to.shared.u64 t, %1; cvt.u32.u64 %0, t; }"
        : "=r"(a) : "l"(p));
    return a;
}

__device__ __forceinline__ void ldsm_x4(uint32_t* r, uint32_t addr) {
    asm volatile("ldmatrix.sync.aligned.m8n8.x4.shared.b16 {%0,%1,%2,%3}, [%4];"
                 : "=r"(r[0]), "=r"(r[1]), "=r"(r[2]), "=r"(r[3]) : "r"(addr));
}

__device__ __forceinline__ void mma_bf16(float* d, const uint32_t* a, const uint32_t* b) {
    asm volatile(
        "mma.sync.aligned.m16n8k16.row.col.f32.bf16.bf16.f32 "
        "{%0,%1,%2,%3}, {%4,%5,%6,%7}, {%8,%9}, {%0,%1,%2,%3};"
        : "+f"(d[0]), "+f"(d[1]), "+f"(d[2]), "+f"(d[3])
        : "r"(a[0]), "r"(a[1]), "r"(a[2]), "r"(a[3]), "r"(b[0]), "r"(b[1]));
}

__device__ __forceinline__ void mma_f16(float* d, const uint32_t* a, const uint32_t* b) {
    asm volatile(
        "mma.sync.aligned.m16n8k16.row.col.f32.f16.f16.f32 "
        "{%0,%1,%2,%3}, {%4,%5,%6,%7}, {%8,%9}, {%0,%1,%2,%3};"
        : "+f"(d[0]), "+f"(d[1]), "+f"(d[2]), "+f"(d[3])
        : "r"(a[0]), "r"(a[1]), "r"(a[2]), "r"(a[3]), "r"(b[0]), "r"(b[1]));
}

#define CP_ASYNC16(dst, src) \
    asm volatile("cp.async.cg.shared.global [%0], [%1], 16;" :: "r"(dst), "l"(src))
#define CP_COMMIT() asm volatile("cp.async.commit_group;" ::: "memory")
#define CP_WAIT0()  asm volatile("cp.async.wait_group 0;" ::: "memory")
#define CP_WAIT1()  asm volatile("cp.async.wait_group 1;" ::: "memory")

#define SW128(bo) ((bo) ^ (((bo) >> 3) & 0x70))

__device__ __forceinline__ void split2(float a, float b,
                                       __nv_bfloat162& hi, __nv_bfloat162& lo) {
    __nv_bfloat16 ha = __float2bfloat16(a), hb = __float2bfloat16(b);
    hi = __halves2bfloat162(ha, hb);
    lo = __halves2bfloat162(__float2bfloat16(a - __bfloat162float(ha)),
                            __float2bfloat16(b - __bfloat162float(hb)));
}

__device__ __forceinline__ void split2h(float a, float b,
                                        __half2& hi, __half2& lo) {
    __half ha = __float2half(a), hb = __float2half(b);
    hi = __halves2half2(ha, hb);
    lo = __halves2half2(__float2half(a - __half2float(ha)),
                        __float2half(b - __half2float(hb)));
}

// ============ bf16 3-pass 128x128 mainloop (small attention GEMMs) ========
#define STAGE_BYTES 65536
#define GEMM_SMEM   (2 * STAGE_BYTES)

__device__ __forceinline__ void mm_tile(
    const __nv_bfloat16* Ahi, const __nv_bfloat16* Alo,
    const __nv_bfloat16* Bhi, const __nv_bfloat16* Blo,
    int lda, int ldb, int chunks, char* smem, float (&acc)[4][4][4])
{
    const uint32_t sbase = smem_u32(smem);
    const int tid  = threadIdx.x;
    const int lane = tid & 31;
    const int w    = tid >> 5;
    const int wm   = (w & 1) * 64;
    const int wn   = (w >> 1) * 32;

    const __nv_bfloat16* gb[4] = {Ahi, Alo, Bhi, Blo};
    const int lds[4] = {lda, lda, ldb, ldb};

    auto stage_load = [&](int buf, int kbase) {
        const uint32_t sp0 = sbase + buf * STAGE_BYTES;
#pragma unroll
        for (int m = 0; m < 4; m++) {
            const __nv_bfloat16* gp = gb[m] + kbase;
            const int ld = lds[m];
            const uint32_t sp = sp0 + m * 16384;
#pragma unroll
            for (int j = 0; j < 4; j++) {
                int id  = j * 256 + tid;
                int row = id >> 3;
                int ch  = id & 7;
                uint32_t bo = row * 128 + ch * 16;
                CP_ASYNC16(sp + SW128(bo), (const char*)(gp + (size_t)row * ld) + ch * 16);
            }
        }
    };

    stage_load(0, 0);
    CP_COMMIT();

    const int a_row  = lane & 15;
    const int a_koff = (lane >> 4) * 16;
    const int b_row  = (lane & 7) + ((lane >> 4) << 3);
    const int b_koff = ((lane >> 3) & 1) * 16;

    for (int c = 0; c < chunks; c++) {
        if (c + 1 < chunks) {
            stage_load((c + 1) & 1, (c + 1) * 64);
            CP_COMMIT();
            CP_WAIT1();
        } else {
            CP_WAIT0();
        }
        __syncthreads();

        const uint32_t sA_hi = sbase + (c & 1) * STAGE_BYTES;
        const uint32_t sA_lo = sA_hi + 16384;
        const uint32_t sB_hi = sA_hi + 32768;
        const uint32_t sB_lo = sA_hi + 49152;

#pragma unroll
        for (int ks = 0; ks < 4; ks++) {
            const int kb2 = ks * 32;
            uint32_t ahi[4][4], alo[4][4], bhi[2][4], blo[2][4];
#pragma unroll
            for (int mt = 0; mt < 4; mt++) {
                uint32_t bo = (wm + mt * 16 + a_row) * 128 + kb2 + a_koff;
                uint32_t sw = SW128(bo);
                ldsm_x4(ahi[mt], sA_hi + sw);
                ldsm_x4(alo[mt], sA_lo + sw);
            }
#pragma unroll
            for (int bt = 0; bt < 2; bt++) {
                uint32_t bo = (wn + bt * 16 + b_row) * 128 + kb2 + b_koff;
                uint32_t sw = SW128(bo);
                ldsm_x4(bhi[bt], sB_hi + sw);
                ldsm_x4(blo[bt], sB_lo + sw);
            }
#pragma unroll
            for (int mt = 0; mt < 4; mt++) {
#pragma unroll
                for (int nt = 0; nt < 4; nt++) {
                    const uint32_t* bh = &bhi[nt >> 1][(nt & 1) * 2];
                    const uint32_t* bl = &blo[nt >> 1][(nt & 1) * 2];
                    mma_bf16(acc[mt][nt], ahi[mt], bh);
                    mma_bf16(acc[mt][nt], ahi[mt], bl);
                    mma_bf16(acc[mt][nt], alo[mt], bh);
                }
            }
        }
        __syncthreads();
    }
}

// ============ fp16 2-pass 128x128 mainloop (big GEMMs) =====================
// C = (Ahi + Alo) . B ; B pre-rounded to fp16.
#define STAGE2_BYTES 49152
#define GEMM2_SMEM   (2 * STAGE2_BYTES)

__device__ __forceinline__ void mm_tile2(
    const __half* Ahi, const __half* Alo, const __half* Bf,
    int lda, int ldb, int chunks, char* smem, float (&acc)[4][4][4])
{
    const uint32_t sbase = smem_u32(smem);
    const int tid  = threadIdx.x;
    const int lane = tid & 31;
    const int w    = tid >> 5;
    const int wm   = (w & 1) * 64;
    const int wn   = (w >> 1) * 32;

    const __half* gb[3] = {Ahi, Alo, Bf};
    const int lds[3] = {lda, lda, ldb};

    auto stage_load = [&](int buf, int kbase) {
        const uint32_t sp0 = sbase + buf * STAGE2_BYTES;
#pragma unroll
        for (int m = 0; m < 3; m++) {
            const __half* gp = gb[m] + kbase;
            const int ld = lds[m];
            const uint32_t sp = sp0 + m * 16384;
#pragma unroll
            for (int j = 0; j < 4; j++) {
                int id  = j * 256 + tid;
                int row = id >> 3;
                int ch  = id & 7;
                uint32_t bo = row * 128 + ch * 16;
                CP_ASYNC16(sp + SW128(bo), (const char*)(gp + (size_t)row * ld) + ch * 16);
            }
        }
    };

    stage_load(0, 0);
    CP_COMMIT();

    const int a_row  = lane & 15;
    const int a_koff = (lane >> 4) * 16;
    const int b_row  = (lane & 7) + ((lane >> 4) << 3);
    const int b_koff = ((lane >> 3) & 1) * 16;

    for (int c = 0; c < chunks; c++) {
        if (c + 1 < chunks) {
            stage_load((c + 1) & 1, (c + 1) * 64);
            CP_COMMIT();
            CP_WAIT1();
        } else {
            CP_WAIT0();
        }
        __syncthreads();

        const uint32_t sA_hi = sbase + (c & 1) * STAGE2_BYTES;
        const uint32_t sA_lo = sA_hi + 16384;
        const uint32_t sB    = sA_hi + 32768;

#pragma unroll
        for (int ks = 0; ks < 4; ks++) {
            const int kb2 = ks * 32;
            uint32_t ahi[4][4], alo[4][4], bf[2][4];
#pragma unroll
            for (int mt = 0; mt < 4; mt++) {
                uint32_t bo = (wm + mt * 16 + a_row) * 128 + kb2 + a_koff;
                uint32_t sw = SW128(bo);
                ldsm_x4(ahi[mt], sA_hi + sw);
                ldsm_x4(alo[mt], sA_lo + sw);
            }
#pragma unroll
            for (int bt = 0; bt < 2; bt++) {
                uint32_t bo = (wn + bt * 16 + b_row) * 128 + kb2 + b_koff;
                uint32_t sw = SW128(bo);
                ldsm_x4(bf[bt], sB + sw);
            }
#pragma unroll
            for (int mt = 0; mt < 4; mt++) {
#pragma unroll
                for (int nt = 0; nt < 4; nt++) {
                    const uint32_t* bp = &bf[nt >> 1][(nt & 1) * 2];
                    mma_f16(acc[mt][nt], ahi[mt], bp);
                    mma_f16(acc[mt][nt], alo[mt], bp);
                }
            }
        }
        __syncthreads();
    }
}

#define ACC_INIT(acc) \
    _Pragma("unroll") for (int i = 0; i < 4; i++) \
    _Pragma("unroll") for (int j = 0; j < 4; j++) \
    _Pragma("unroll") for (int q = 0; q < 4; q++) acc[i][j][q] = 0.f;

// ============ fused QKV GEMM (fp16 2-pass): grid (48, 32) ==================
__global__ void __launch_bounds__(256)
gemm_qkv(const __half* __restrict__ xhi, const __half* __restrict__ xlo,
         const __half* __restrict__ wf,
         const float* __restrict__ bq, const float* __restrict__ bk,
         const float* __restrict__ bv,
         float* __restrict__ pQ, float* __restrict__ pK, float* __restrict__ pV)
{
    extern __shared__ char smem[];
    const int bx = blockIdx.x, by = blockIdx.y;
    const int wsel = bx >> 4;
    const int col0 = (bx & 15) * 128;
    const int row0 = by * 128;
    const float* bias = (wsel == 0) ? bq : ((wsel == 1) ? bk : bv);
    float* C = (wsel == 0) ? pQ : ((wsel == 1) ? pK : pV);

    float acc[4][4][4];
    ACC_INIT(acc)
    mm_tile2(xhi + (size_t)row0 * DIM_, xlo + (size_t)row0 * DIM_,
             wf + (size_t)bx * 128 * DIM_,
             DIM_, DIM_, DIM_ / 64, smem, acc);

    const int lane = threadIdx.x & 31, w = threadIdx.x >> 5;
    const int wm = (w & 1) * 64, wn = (w >> 1) * 32;
    const int l4 = lane >> 2, l2 = (lane & 3) * 2;
#pragma unroll
    for (int mt = 0; mt < 4; mt++) {
#pragma unroll
        for (int nt = 0; nt < 4; nt++) {
            int grow = row0 + wm + mt * 16 + l4;
            int gcol = col0 + wn + nt * 8 + l2;
            float b0 = __ldg(bias + gcol);
            float b1 = __ldg(bias + gcol + 1);
            float* cp0 = C + (size_t)grow * DIM_ + gcol;
            float* cp1 = cp0 + 8 * (size_t)DIM_;
            *(float2*)cp0 = make_float2(acc[mt][nt][0] + b0, acc[mt][nt][1] + b1);
            *(float2*)cp1 = make_float2(acc[mt][nt][2] + b0, acc[mt][nt][3] + b1);
        }
    }
}

// ============ WO GEMM (fp16 2-pass): grid (16, 32) =========================
__global__ void __launch_bounds__(256)
gemm_wo(const __half* __restrict__ Ahi, const __half* __restrict__ Alo,
        const __half* __restrict__ Bf,
        const float* __restrict__ bias, float* __restrict__ C)
{
    extern __shared__ char smem[];
    const int row0 = blockIdx.y * 128;
    const int col0 = blockIdx.x * 128;

    float acc[4][4][4];
    ACC_INIT(acc)
    mm_tile2(Ahi + (size_t)row0 * DIM_, Alo + (size_t)row0 * DIM_,
             Bf + (size_t)col0 * DIM_,
             DIM_, DIM_, DIM_ / 64, smem, acc);

    const int lane = threadIdx.x & 31, w = threadIdx.x >> 5;
    const int wm = (w & 1) * 64, wn = (w >> 1) * 32;
    const int l4 = lane >> 2, l2 = (lane & 3) * 2;
#pragma unroll
    for (int mt = 0; mt < 4; mt++) {
#pragma unroll
        for (int nt = 0; nt < 4; nt++) {
            int grow = row0 + wm + mt * 16 + l4;
            int gcol = col0 + wn + nt * 8 + l2;
            float b0 = __ldg(bias + gcol);
            float b1 = __ldg(bias + gcol + 1);
            float* cp0 = C + (size_t)grow * DIM_ + gcol;
            float* cp1 = cp0 + 8 * (size_t)DIM_;
            *(float2*)cp0 = make_float2(acc[mt][nt][0] + b0, acc[mt][nt][1] + b1);
            *(float2*)cp1 = make_float2(acc[mt][nt][2] + b0, acc[mt][nt][3] + b1);
        }
    }
}

// ============ KtV GEMM (bf16 3-pass): grid (KVSPLIT, 32) ===================
__global__ void __launch_bounds__(256)
kv_hmma(const __nv_bfloat16* __restrict__ kthi, const __nv_bfloat16* __restrict__ ktlo,
        const __nv_bfloat16* __restrict__ vthi, const __nv_bfloat16* __restrict__ vtlo,
        float* __restrict__ Mp)
{
    extern __shared__ char smem[];
    const int ksp = blockIdx.x;
    const int bh  = blockIdx.y;
    const size_t base = (size_t)bh * HD_ * S_ + ksp * (S_ / KVSPLIT);

    float acc[4][4][4];
    ACC_INIT(acc)
    mm_tile(kthi + base, ktlo + base, vthi + base, vtlo + base,
            S_, S_, (S_ / KVSPLIT) / 64, smem, acc);

    float* C = Mp + ((size_t)ksp * 32 + bh) * (HD_ * HD_);
    const int lane = threadIdx.x & 31, w = threadIdx.x >> 5;
    const int wm = (w & 1) * 64, wn = (w >> 1) * 32;
    const int l4 = lane >> 2, l2 = (lane & 3) * 2;
#pragma unroll
    for (int mt = 0; mt < 4; mt++) {
#pragma unroll
        for (int nt = 0; nt < 4; nt++) {
            int grow = wm + mt * 16 + l4;
            int gcol = wn + nt * 8 + l2;
            float* cp0 = C + (size_t)grow * HD_ + gcol;
            float* cp1 = cp0 + 8 * HD_;
            *(float2*)cp0 = make_float2(acc[mt][nt][0], acc[mt][nt][1]);
            *(float2*)cp1 = make_float2(acc[mt][nt][2], acc[mt][nt][3]);
        }
    }
}

// ============ attn GEMM (bf16 3-pass, fp16 split output): grid (16,32) =====
__global__ void __launch_bounds__(256)
attn_hmma(const __nv_bfloat16* __restrict__ qhi, const __nv_bfloat16* __restrict__ qlo,
          const __nv_bfloat16* __restrict__ mthi, const __nv_bfloat16* __restrict__ mtlo,
          __half* __restrict__ ahi, __half* __restrict__ alo)
{
    extern __shared__ char smem[];
    const int st = blockIdx.x;
    const int bh = blockIdx.y;
    const int b = bh >> 4, h = bh & 15;
    const size_t abase = ((size_t)(b * S_ + st * 128)) * DIM_ + h * HD_;
    const size_t mbase = (size_t)bh * HD_ * HD_;

    float acc[4][4][4];
    ACC_INIT(acc)
    mm_tile(qhi + abase, qlo + abase, mthi + mbase, mtlo + mbase,
            DIM_, HD_, HD_ / 64, smem, acc);

    const int lane = threadIdx.x & 31, w = threadIdx.x >> 5;
    const int wm = (w & 1) * 64, wn = (w >> 1) * 32;
    const int l4 = lane >> 2, l2 = (lane & 3) * 2;
#pragma unroll
    for (int mt = 0; mt < 4; mt++) {
#pragma unroll
        for (int nt = 0; nt < 4; nt++) {
            size_t off0 = abase + (size_t)(wm + mt * 16 + l4) * DIM_ + wn + nt * 8 + l2;
            size_t off1 = off0 + 8 * (size_t)DIM_;
            __half2 hi, lo;
            split2h(acc[mt][nt][0], acc[mt][nt][1], hi, lo);
            *(__half2*)(ahi + off0) = hi;
            *(__half2*)(alo + off0) = lo;
            split2h(acc[mt][nt][2], acc[mt][nt][3], hi, lo);
            *(__half2*)(ahi + off1) = hi;
            *(__half2*)(alo + off1) = lo;
        }
    }
}

// ============ prep: rope+split Q (row), rope+transpose-split K, ============
// ============       transpose-split V. grid (16, 32), 256 thr. ============
#define PREP_SMEM (2 * 128 * 132 * 2)

__global__ void __launch_bounds__(256)
prep_qkv(const float* __restrict__ Q, const float* __restrict__ K,
         const float* __restrict__ V,
         const float* __restrict__ fc, const float* __restrict__ fs,
         __nv_bfloat16* __restrict__ qhi, __nv_bfloat16* __restrict__ qlo,
         __nv_bfloat16* __restrict__ kthi, __nv_bfloat16* __restrict__ ktlo,
         __nv_bfloat16* __restrict__ vthi, __nv_bfloat16* __restrict__ vtlo)
{
    extern __shared__ __nv_bfloat16 sm[];
    __nv_bfloat16* shi = sm;
    __nv_bfloat16* slo = sm + 128 * 132;

    const int st = blockIdx.x;
    const int bh = blockIdx.y;
    const int b = bh >> 4, h = bh & 15;
    const int s0 = st * 128;
    const int tid = threadIdx.x;
    const size_t rowbase = ((size_t)(b * S_ + s0)) * DIM_ + h * HD_;
    const size_t tbase = (size_t)bh * HD_ * S_ + s0;

    // ---- Q: rope + split, row-major ----
    for (int idx = tid; idx < 128 * 64; idx += 256) {
        int sl = idx >> 6, i = idx & 63;
        int sg = s0 + sl;
        float c = fc[sg * 64 + i], sn = fs[sg * 64 + i];
        size_t off = rowbase + (size_t)sl * DIM_ + 2 * i;
        float2 q = *(const float2*)(Q + off);
        float o0 = q.x * c - q.y * sn, o1 = q.x * sn + q.y * c;
        __nv_bfloat162 hi, lo;
        split2(o0, o1, hi, lo);
        *(__nv_bfloat162*)(qhi + off) = hi;
        *(__nv_bfloat162*)(qlo + off) = lo;
    }

    // ---- K: rope + split into smem ----
    for (int idx = tid; idx < 128 * 64; idx += 256) {
        int sl = idx >> 6, i = idx & 63;
        int sg = s0 + sl;
        float c = fc[sg * 64 + i], sn = fs[sg * 64 + i];
        float2 k = *(const float2*)(K + rowbase + (size_t)sl * DIM_ + 2 * i);
        float o0 = k.x * c - k.y * sn, o1 = k.x * sn + k.y * c;
        __nv_bfloat162 hi, lo;
        split2(o0, o1, hi, lo);
        *(__nv_bfloat162*)(shi + sl * 132 + 2 * i) = hi;
        *(__nv_bfloat162*)(slo + sl * 132 + 2 * i) = lo;
    }
    __syncthreads();
    for (int idx = tid; idx < 128 * 64; idx += 256) {
        int d = idx >> 6;
        int sp = (idx & 63) * 2;
        __nv_bfloat162 vh = __halves2bfloat162(shi[sp * 132 + d], shi[(sp + 1) * 132 + d]);
        __nv_bfloat162 vl = __halves2bfloat162(slo[sp * 132 + d], slo[(sp + 1) * 132 + d]);
        size_t off = tbase + (size_t)d * S_ + sp;
        *(__nv_bfloat162*)(kthi + off) = vh;
        *(__nv_bfloat162*)(ktlo + off) = vl;
    }
    __syncthreads();

    // ---- V: split into smem (no rope) ----
    for (int idx = tid; idx < 128 * 64; idx += 256) {
        int sl = idx >> 6, i = idx & 63;
        float2 v = *(const float2*)(V + rowbase + (size_t)sl * DIM_ + 2 * i);
        __nv_bfloat162 hi, lo;
        split2(v.x, v.y, hi, lo);
        *(__nv_bfloat162*)(shi + sl * 132 + 2 * i) = hi;
        *(__nv_bfloat162*)(slo + sl * 132 + 2 * i) = lo;
    }
    __syncthreads();
    for (int idx = tid; idx < 128 * 64; idx += 256) {
        int d = idx >> 6;
        int sp = (idx & 63) * 2;
        __nv_bfloat162 vh = __halves2bfloat162(shi[sp * 132 + d], shi[(sp + 1) * 132 + d]);
        __nv_bfloat162 vl = __halves2bfloat162(slo[sp * 132 + d], slo[(sp + 1) * 132 + d]);
        size_t off = tbase + (size_t)d * S_ + sp;
        *(__nv_bfloat162*)(vthi + off) = vh;
        *(__nv_bfloat162*)(vtlo + off) = vl;
    }
}

// ============ reduce Mp over splits, scale, transpose, split ===============
__global__ void reduce_mt(const float* __restrict__ Mp,
                          __nv_bfloat16* __restrict__ mthi,
                          __nv_bfloat16* __restrict__ mtlo)
{
    int o = blockIdx.x * 256 + threadIdx.x;
    int bh = o >> 13;
    int r  = o & 8191;
    int d  = r >> 6;
    int d2p = (r & 63) * 2;
    const float* src = Mp + (size_t)bh * (HD_ * HD_) + (size_t)d2p * HD_ + d;
    float s0 = 0.f, s1 = 0.f;
    const size_t stride = (size_t)32 * HD_ * HD_;
#pragma unroll
    for (int p = 0; p < KVSPLIT; p++) {
        s0 += src[p * stride];
        s1 += src[p * stride + HD_];
    }
    s0 *= 0.08838834764831845f;
    s1 *= 0.08838834764831845f;
    __nv_bfloat162 hi, lo;
    split2(s0, s1, hi, lo);
    size_t off = (size_t)bh * (HD_ * HD_) + (size_t)d * HD_ + d2p;
    *(__nv_bfloat162*)(mthi + off) = hi;
    *(__nv_bfloat162*)(mtlo + off) = lo;
}

// ---------------- fp32 -> fp16 hi/lo split ---------------------------------
__global__ void split_fp32_fp16(const float* __restrict__ x,
                                __half* __restrict__ hi,
                                __half* __restrict__ lo, int n)
{
    int i = (blockIdx.x * 256 + threadIdx.x) * 4;
    if (i >= n) return;
    float4 v = *(const float4*)(x + i);
    __half2 h01, l01, h23, l23;
    split2h(v.x, v.y, h01, l01);
    split2h(v.z, v.w, h23, l23);
    ((__half2*)(hi + i))[0] = h01;
    ((__half2*)(hi + i))[1] = h23;
    ((__half2*)(lo + i))[0] = l01;
    ((__half2*)(lo + i))[1] = l23;
}

// ---------------- fp32 -> fp16 round ---------------------------------------
__global__ void round_fp32_fp16(const float* __restrict__ x,
                                __half* __restrict__ o, int n)
{
    int i = (blockIdx.x * 256 + threadIdx.x) * 4;
    if (i >= n) return;
    float4 v = *(const float4*)(x + i);
    ((__half2*)(o + i))[0] = __floats2half2_rn(v.x, v.y);
    ((__half2*)(o + i))[1] = __floats2half2_rn(v.z, v.w);
}

// ---------------------------------------------------------------------------
extern "C" void kernel_launch(void* const* d_in, const int* in_sizes, int n_in,
                              void* d_out, int out_size)
{
    const float* x  = (const float*)d_in[0];
    const float* fc = (const float*)d_in[1];
    const float* fs = (const float*)d_in[2];
    const float* wq = (const float*)d_in[3];
    const float* bq = (const float*)d_in[4];
    const float* wk = (const float*)d_in[5];
    const float* bk = (const float*)d_in[6];
    const float* wv = (const float*)d_in[7];
    const float* bv = (const float*)d_in[8];
    const float* wo = (const float*)d_in[9];
    const float* bo = (const float*)d_in[10];
    float* out = (float*)d_out;

    float *pQ, *pK, *pV, *pMp;
    __half *pxh, *pxl, *pw, *pah, *pal;
    __nv_bfloat16 *pqh, *pql, *pkth, *pktl, *pvth, *pvtl, *pmth, *pmtl;
    cudaGetSymbolAddress((void**)&pQ,  g_Q);
    cudaGetSymbolAddress((void**)&pK,  g_K);
    cudaGetSymbolAddress((void**)&pV,  g_V);
    cudaGetSymbolAddress((void**)&pMp, g_Mp);
    cudaGetSymbolAddress((void**)&pxh, g_xhi);
    cudaGetSymbolAddress((void**)&pxl, g_xlo);
    cudaGetSymbolAddress((void**)&pw,  g_w);
    cudaGetSymbolAddress((void**)&pah, g_ahi);
    cudaGetSymbolAddress((void**)&pal, g_alo);
    cudaGetSymbolAddress((void**)&pqh, g_qhi);
    cudaGetSymbolAddress((void**)&pql, g_qlo);
    cudaGetSymbolAddress((void**)&pkth, g_kthi);
    cudaGetSymbolAddress((void**)&pktl, g_ktlo);
    cudaGetSymbolAddress((void**)&pvth, g_vthi);
    cudaGetSymbolAddress((void**)&pvtl, g_vtlo);
    cudaGetSymbolAddress((void**)&pmth, g_mthi);
    cudaGetSymbolAddress((void**)&pmtl, g_mtlo);

    cudaFuncSetAttribute(gemm_qkv,  cudaFuncAttributeMaxDynamicSharedMemorySize, GEMM2_SMEM);
    cudaFuncSetAttribute(gemm_wo,   cudaFuncAttributeMaxDynamicSharedMemorySize, GEMM2_SMEM);
    cudaFuncSetAttribute(kv_hmma,   cudaFuncAttributeMaxDynamicSharedMemorySize, GEMM_SMEM);
    cudaFuncSetAttribute(attn_hmma, cudaFuncAttributeMaxDynamicSharedMemorySize, GEMM_SMEM);
    cudaFuncSetAttribute(prep_qkv,  cudaFuncAttributeMaxDynamicSharedMemorySize, PREP_SMEM);

    dim3 blk(256);
    const int NX = MROWS * DIM_;
    const int NW = DIM_ * DIM_;
    const size_t WSTRIDE = (size_t)DIM_ * DIM_;

    split_fp32_fp16<<<NX / 1024, blk>>>(x, pxh, pxl, NX);
    round_fp32_fp16<<<NW / 1024, blk>>>(wq, pw + 0 * WSTRIDE, NW);
    round_fp32_fp16<<<NW / 1024, blk>>>(wk, pw + 1 * WSTRIDE, NW);
    round_fp32_fp16<<<NW / 1024, blk>>>(wv, pw + 2 * WSTRIDE, NW);
    round_fp32_fp16<<<NW / 1024, blk>>>(wo, pw + 3 * WSTRIDE, NW);

    gemm_qkv<<<dim3(48, 32), blk, GEMM2_SMEM>>>(pxh, pxl, pw,
                                                bq, bk, bv, pQ, pK, pV);

    prep_qkv<<<dim3(16, 32), blk, PREP_SMEM>>>(pQ, pK, pV, fc, fs,
                                               pqh, pql, pkth, pktl, pvth, pvtl);

    kv_hmma<<<dim3(KVSPLIT, 32), blk, GEMM_SMEM>>>(pkth, pktl, pvth, pvtl, pMp);

    reduce_mt<<<(32 * HD_ * HD_ / 2) / 256, blk>>>(pMp, pmth, pmtl);

    attn_hmma<<<dim3(16, 32), blk, GEMM_SMEM>>>(pqh, pql, pmth, pmtl, pah, pal);

    gemm_wo<<<dim3(16, 32), blk, GEMM2_SMEM>>>(pah, pal, pw + 3 * WSTRIDE,
                                               bo, out);
}

// round 8
// speedup vs baseline: 4.6392x; 1.1347x over previous
#include <cuda_runtime.h>
#include <cuda_fp16.h>
#include <cstdint>

#define B_  2
#define S_  2048
#define DIM_ 2048
#define NH_ 16
#define HD_ 128
#define MROWS (B_*S_)          // 4096
#define KVSPLIT 8
#define NW_ (DIM_*DIM_)        // 4194304 = 2^22

// ---------------- scratch (device globals; no allocation) ----------------
__device__ __align__(16) float g_Q[(size_t)MROWS * DIM_];
__device__ __align__(16) float g_K[(size_t)MROWS * DIM_];
__device__ __align__(16) float g_V[(size_t)MROWS * DIM_];
__device__ __align__(16) float g_Mp[(size_t)KVSPLIT * B_ * NH_ * HD_ * HD_];

__device__ __align__(16) __half g_xhi[(size_t)MROWS * DIM_];
__device__ __align__(16) __half g_xlo[(size_t)MROWS * DIM_];
__device__ __align__(16) __half g_w[4][(size_t)NW_];
__device__ __align__(16) __half g_ahi[(size_t)MROWS * DIM_];
__device__ __align__(16) __half g_alo[(size_t)MROWS * DIM_];

__device__ __align__(16) __half g_qhi[(size_t)MROWS * DIM_];
__device__ __align__(16) __half g_qlo[(size_t)MROWS * DIM_];
__device__ __align__(16) __half g_kthi[(size_t)B_ * NH_ * HD_ * S_];
__device__ __align__(16) __half g_ktlo[(size_t)B_ * NH_ * HD_ * S_];
__device__ __align__(16) __half g_vt [(size_t)B_ * NH_ * HD_ * S_];
__device__ __align__(16) __half g_mt [(size_t)B_ * NH_ * HD_ * HD_];

// ======================= PTX helpers ==========================
__device__ __forceinline__ uint32_t smem_u32(const void* p) {
    uint32_t a;
    asm("{ .reg .u64 t; cvta.to.shared.u64 t, %1; cvt.u32.u64 %0, t; }"
        : "=r"(a) : "l"(p));
    return a;
}

__device__ __forceinline__ void ldsm_x4(uint32_t* r, uint32_t addr) {
    asm volatile("ldmatrix.sync.aligned.m8n8.x4.shared.b16 {%0,%1,%2,%3}, [%4];"
                 : "=r"(r[0]), "=r"(r[1]), "=r"(r[2]), "=r"(r[3]) : "r"(addr));
}

__device__ __forceinline__ void mma_f16(float* d, const uint32_t* a, const uint32_t* b) {
    asm volatile(
        "mma.sync.aligned.m16n8k16.row.col.f32.f16.f16.f32 "
        "{%0,%1,%2,%3}, {%4,%5,%6,%7}, {%8,%9}, {%0,%1,%2,%3};"
        : "+f"(d[0]), "+f"(d[1]), "+f"(d[2]), "+f"(d[3])
        : "r"(a[0]), "r"(a[1]), "r"(a[2]), "r"(a[3]), "r"(b[0]), "r"(b[1]));
}

#define CP_ASYNC16(dst, src) \
    asm volatile("cp.async.cg.shared.global [%0], [%1], 16;" :: "r"(dst), "l"(src))
#define CP_COMMIT() asm volatile("cp.async.commit_group;" ::: "memory")
#define CP_WAIT0()  asm volatile("cp.async.wait_group 0;" ::: "memory")
#define CP_WAIT1()  asm volatile("cp.async.wait_group 1;" ::: "memory")

#define SW128(bo) ((bo) ^ (((bo) >> 3) & 0x70))

__device__ __forceinline__ void split2h(float a, float b,
                                        __half2& hi, __half2& lo) {
    __half ha = __float2half(a), hb = __float2half(b);
    hi = __halves2half2(ha, hb);
    lo = __halves2half2(__float2half(a - __half2float(ha)),
                        __float2half(b - __half2float(hb)));
}

// ============ fp16 2-pass 128x128 mainloop =====================
// C = (Ahi + Alo) . B ; B pre-rounded to fp16.
#define STAGE2_BYTES 49152
#define GEMM2_SMEM   (2 * STAGE2_BYTES)

__device__ __forceinline__ void mm_tile2(
    const __half* Ahi, const __half* Alo, const __half* Bf,
    int lda, int ldb, int chunks, char* smem, float (&acc)[4][4][4])
{
    const uint32_t sbase = smem_u32(smem);
    const int tid  = threadIdx.x;
    const int lane = tid & 31;
    const int w    = tid >> 5;
    const int wm   = (w & 1) * 64;
    const int wn   = (w >> 1) * 32;

    const __half* gb[3] = {Ahi, Alo, Bf};
    const int lds[3] = {lda, lda, ldb};

    auto stage_load = [&](int buf, int kbase) {
        const uint32_t sp0 = sbase + buf * STAGE2_BYTES;
#pragma unroll
        for (int m = 0; m < 3; m++) {
            const __half* gp = gb[m] + kbase;
            const int ld = lds[m];
            const uint32_t sp = sp0 + m * 16384;
#pragma unroll
            for (int j = 0; j < 4; j++) {
                int id  = j * 256 + tid;
                int row = id >> 3;
                int ch  = id & 7;
                uint32_t bo = row * 128 + ch * 16;
                CP_ASYNC16(sp + SW128(bo), (const char*)(gp + (size_t)row * ld) + ch * 16);
            }
        }
    };

    stage_load(0, 0);
    CP_COMMIT();

    const int a_row  = lane & 15;
    const int a_koff = (lane >> 4) * 16;
    const int b_row  = (lane & 7) + ((lane >> 4) << 3);
    const int b_koff = ((lane >> 3) & 1) * 16;

    for (int c = 0; c < chunks; c++) {
        if (c + 1 < chunks) {
            stage_load((c + 1) & 1, (c + 1) * 64);
            CP_COMMIT();
            CP_WAIT1();
        } else {
            CP_WAIT0();
        }
        __syncthreads();

        const uint32_t sA_hi = sbase + (c & 1) * STAGE2_BYTES;
        const uint32_t sA_lo = sA_hi + 16384;
        const uint32_t sB    = sA_hi + 32768;

#pragma unroll
        for (int ks = 0; ks < 4; ks++) {
            const int kb2 = ks * 32;
            uint32_t ahi[4][4], alo[4][4], bf[2][4];
#pragma unroll
            for (int mt = 0; mt < 4; mt++) {
                uint32_t bo = (wm + mt * 16 + a_row) * 128 + kb2 + a_koff;
                uint32_t sw = SW128(bo);
                ldsm_x4(ahi[mt], sA_hi + sw);
                ldsm_x4(alo[mt], sA_lo + sw);
            }
#pragma unroll
            for (int bt = 0; bt < 2; bt++) {
                uint32_t bo = (wn + bt * 16 + b_row) * 128 + kb2 + b_koff;
                uint32_t sw = SW128(bo);
                ldsm_x4(bf[bt], sB + sw);
            }
#pragma unroll
            for (int mt = 0; mt < 4; mt++) {
#pragma unroll
                for (int nt = 0; nt < 4; nt++) {
                    const uint32_t* bp = &bf[nt >> 1][(nt & 1) * 2];
                    mma_f16(acc[mt][nt], ahi[mt], bp);
                    mma_f16(acc[mt][nt], alo[mt], bp);
                }
            }
        }
        __syncthreads();
    }
}

#define ACC_INIT(acc) \
    _Pragma("unroll") for (int i = 0; i < 4; i++) \
    _Pragma("unroll") for (int j = 0; j < 4; j++) \
    _Pragma("unroll") for (int q = 0; q < 4; q++) acc[i][j][q] = 0.f;

// ============ fused QKV GEMM: grid (48, 32) ================================
__global__ void __launch_bounds__(256, 2)
gemm_qkv(const __half* __restrict__ xhi, const __half* __restrict__ xlo,
         const __half* __restrict__ wf,
         const float* __restrict__ bq, const float* __restrict__ bk,
         const float* __restrict__ bv,
         float* __restrict__ pQ, float* __restrict__ pK, float* __restrict__ pV)
{
    extern __shared__ char smem[];
    const int bx = blockIdx.x, by = blockIdx.y;
    const int wsel = bx >> 4;
    const int col0 = (bx & 15) * 128;
    const int row0 = by * 128;
    const float* bias = (wsel == 0) ? bq : ((wsel == 1) ? bk : bv);
    float* C = (wsel == 0) ? pQ : ((wsel == 1) ? pK : pV);

    float acc[4][4][4];
    ACC_INIT(acc)
    mm_tile2(xhi + (size_t)row0 * DIM_, xlo + (size_t)row0 * DIM_,
             wf + (size_t)bx * 128 * DIM_,
             DIM_, DIM_, DIM_ / 64, smem, acc);

    const int lane = threadIdx.x & 31, w = threadIdx.x >> 5;
    const int wm = (w & 1) * 64, wn = (w >> 1) * 32;
    const int l4 = lane >> 2, l2 = (lane & 3) * 2;
#pragma unroll
    for (int mt = 0; mt < 4; mt++) {
#pragma unroll
        for (int nt = 0; nt < 4; nt++) {
            int grow = row0 + wm + mt * 16 + l4;
            int gcol = col0 + wn + nt * 8 + l2;
            float b0 = __ldg(bias + gcol);
            float b1 = __ldg(bias + gcol + 1);
            float* cp0 = C + (size_t)grow * DIM_ + gcol;
            float* cp1 = cp0 + 8 * (size_t)DIM_;
            *(float2*)cp0 = make_float2(acc[mt][nt][0] + b0, acc[mt][nt][1] + b1);
            *(float2*)cp1 = make_float2(acc[mt][nt][2] + b0, acc[mt][nt][3] + b1);
        }
    }
}

// ============ WO GEMM: grid (16, 32) =======================================
__global__ void __launch_bounds__(256, 2)
gemm_wo(const __half* __restrict__ Ahi, const __half* __restrict__ Alo,
        const __half* __restrict__ Bf,
        const float* __restrict__ bias, float* __restrict__ C)
{
    extern __shared__ char smem[];
    const int row0 = blockIdx.y * 128;
    const int col0 = blockIdx.x * 128;

    float acc[4][4][4];
    ACC_INIT(acc)
    mm_tile2(Ahi + (size_t)row0 * DIM_, Alo + (size_t)row0 * DIM_,
             Bf + (size_t)col0 * DIM_,
             DIM_, DIM_, DIM_ / 64, smem, acc);

    const int lane = threadIdx.x & 31, w = threadIdx.x >> 5;
    const int wm = (w & 1) * 64, wn = (w >> 1) * 32;
    const int l4 = lane >> 2, l2 = (lane & 3) * 2;
#pragma unroll
    for (int mt = 0; mt < 4; mt++) {
#pragma unroll
        for (int nt = 0; nt < 4; nt++) {
            int grow = row0 + wm + mt * 16 + l4;
            int gcol = col0 + wn + nt * 8 + l2;
            float b0 = __ldg(bias + gcol);
            float b1 = __ldg(bias + gcol + 1);
            float* cp0 = C + (size_t)grow * DIM_ + gcol;
            float* cp1 = cp0 + 8 * (size_t)DIM_;
            *(float2*)cp0 = make_float2(acc[mt][nt][0] + b0, acc[mt][nt][1] + b1);
            *(float2*)cp1 = make_float2(acc[mt][nt][2] + b0, acc[mt][nt][3] + b1);
        }
    }
}

// ============ KtV GEMM (fp16 2-pass): grid (KVSPLIT, 32) ===================
// Mp[ks][bh][d1][d2] = sum_{s chunk} K[s,d1] V[s,d2]; Kt split, Vt rounded.
__global__ void __launch_bounds__(256, 2)
kv_hmma(const __half* __restrict__ kthi, const __half* __restrict__ ktlo,
        const __half* __restrict__ vt, float* __restrict__ Mp)
{
    extern __shared__ char smem[];
    const int ksp = blockIdx.x;
    const int bh  = blockIdx.y;
    const size_t base = (size_t)bh * HD_ * S_ + ksp * (S_ / KVSPLIT);

    float acc[4][4][4];
    ACC_INIT(acc)
    mm_tile2(kthi + base, ktlo + base, vt + base,
             S_, S_, (S_ / KVSPLIT) / 64, smem, acc);

    float* C = Mp + ((size_t)ksp * 32 + bh) * (HD_ * HD_);
    const int lane = threadIdx.x & 31, w = threadIdx.x >> 5;
    const int wm = (w & 1) * 64, wn = (w >> 1) * 32;
    const int l4 = lane >> 2, l2 = (lane & 3) * 2;
#pragma unroll
    for (int mt = 0; mt < 4; mt++) {
#pragma unroll
        for (int nt = 0; nt < 4; nt++) {
            int grow = wm + mt * 16 + l4;
            int gcol = wn + nt * 8 + l2;
            float* cp0 = C + (size_t)grow * HD_ + gcol;
            float* cp1 = cp0 + 8 * HD_;
            *(float2*)cp0 = make_float2(acc[mt][nt][0], acc[mt][nt][1]);
            *(float2*)cp1 = make_float2(acc[mt][nt][2], acc[mt][nt][3]);
        }
    }
}

// ============ attn GEMM (fp16 2-pass): grid (16,32) ========================
__global__ void __launch_bounds__(256, 2)
attn_hmma(const __half* __restrict__ qhi, const __half* __restrict__ qlo,
          const __half* __restrict__ mt_, 
          __half* __restrict__ ahi, __half* __restrict__ alo)
{
    extern __shared__ char smem[];
    const int st = blockIdx.x;
    const int bh = blockIdx.y;
    const int b = bh >> 4, h = bh & 15;
    const size_t abase = ((size_t)(b * S_ + st * 128)) * DIM_ + h * HD_;
    const size_t mbase = (size_t)bh * HD_ * HD_;

    float acc[4][4][4];
    ACC_INIT(acc)
    mm_tile2(qhi + abase, qlo + abase, mt_ + mbase,
             DIM_, HD_, HD_ / 64, smem, acc);

    const int lane = threadIdx.x & 31, w = threadIdx.x >> 5;
    const int wm = (w & 1) * 64, wn = (w >> 1) * 32;
    const int l4 = lane >> 2, l2 = (lane & 3) * 2;
#pragma unroll
    for (int mt = 0; mt < 4; mt++) {
#pragma unroll
        for (int nt = 0; nt < 4; nt++) {
            size_t off0 = abase + (size_t)(wm + mt * 16 + l4) * DIM_ + wn + nt * 8 + l2;
            size_t off1 = off0 + 8 * (size_t)DIM_;
            __half2 hi, lo;
            split2h(acc[mt][nt][0], acc[mt][nt][1], hi, lo);
            *(__half2*)(ahi + off0) = hi;
            *(__half2*)(alo + off0) = lo;
            split2h(acc[mt][nt][2], acc[mt][nt][3], hi, lo);
            *(__half2*)(ahi + off1) = hi;
            *(__half2*)(alo + off1) = lo;
        }
    }
}

// ============ prep: rope+split Q (row), rope+transpose-split K, ============
// ============       transpose-round V. grid (16, 32), 256 thr. ============
#define PREP_SMEM (2 * 128 * 132 * 2)

__global__ void __launch_bounds__(256)
prep_qkv(const float* __restrict__ Q, const float* __restrict__ K,
         const float* __restrict__ V,
         const float* __restrict__ fc, const float* __restrict__ fs,
         __half* __restrict__ qhi, __half* __restrict__ qlo,
         __half* __restrict__ kthi, __half* __restrict__ ktlo,
         __half* __restrict__ vt)
{
    extern __shared__ __half sm[];
    __half* shi = sm;
    __half* slo = sm + 128 * 132;

    const int st = blockIdx.x;
    const int bh = blockIdx.y;
    const int b = bh >> 4, h = bh & 15;
    const int s0 = st * 128;
    const int tid = threadIdx.x;
    const size_t rowbase = ((size_t)(b * S_ + s0)) * DIM_ + h * HD_;
    const size_t tbase = (size_t)bh * HD_ * S_ + s0;

    // ---- Q: rope + split, row-major ----
    for (int idx = tid; idx < 128 * 64; idx += 256) {
        int sl = idx >> 6, i = idx & 63;
        int sg = s0 + sl;
        float c = fc[sg * 64 + i], sn = fs[sg * 64 + i];
        size_t off = rowbase + (size_t)sl * DIM_ + 2 * i;
        float2 q = *(const float2*)(Q + off);
        float o0 = q.x * c - q.y * sn, o1 = q.x * sn + q.y * c;
        __half2 hi, lo;
        split2h(o0, o1, hi, lo);
        *(__half2*)(qhi + off) = hi;
        *(__half2*)(qlo + off) = lo;
    }

    // ---- K: rope + split into smem, transposed write ----
    for (int idx = tid; idx < 128 * 64; idx += 256) {
        int sl = idx >> 6, i = idx & 63;
        int sg = s0 + sl;
        float c = fc[sg * 64 + i], sn = fs[sg * 64 + i];
        float2 k = *(const float2*)(K + rowbase + (size_t)sl * DIM_ + 2 * i);
        float o0 = k.x * c - k.y * sn, o1 = k.x * sn + k.y * c;
        __half2 hi, lo;
        split2h(o0, o1, hi, lo);
        *(__half2*)(shi + sl * 132 + 2 * i) = hi;
        *(__half2*)(slo + sl * 132 + 2 * i) = lo;
    }
    __syncthreads();
    for (int idx = tid; idx < 128 * 64; idx += 256) {
        int d = idx >> 6;
        int sp = (idx & 63) * 2;
        __half2 vh = __halves2half2(shi[sp * 132 + d], shi[(sp + 1) * 132 + d]);
        __half2 vl = __halves2half2(slo[sp * 132 + d], slo[(sp + 1) * 132 + d]);
        size_t off = tbase + (size_t)d * S_ + sp;
        *(__half2*)(kthi + off) = vh;
        *(__half2*)(ktlo + off) = vl;
    }
    __syncthreads();

    // ---- V: round into smem, transposed write ----
    for (int idx = tid; idx < 128 * 64; idx += 256) {
        int sl = idx >> 6, i = idx & 63;
        float2 v = *(const float2*)(V + rowbase + (size_t)sl * DIM_ + 2 * i);
        *(__half2*)(shi + sl * 132 + 2 * i) = __floats2half2_rn(v.x, v.y);
    }
    __syncthreads();
    for (int idx = tid; idx < 128 * 64; idx += 256) {
        int d = idx >> 6;
        int sp = (idx & 63) * 2;
        __half2 vh = __halves2half2(shi[sp * 132 + d], shi[(sp + 1) * 132 + d]);
        size_t off = tbase + (size_t)d * S_ + sp;
        *(__half2*)(vt + off) = vh;
    }
}

// ============ reduce Mp over splits, scale, transpose, round ===============
__global__ void reduce_mt(const float* __restrict__ Mp, __half* __restrict__ mt)
{
    int o = blockIdx.x * 256 + threadIdx.x;
    int bh = o >> 13;
    int r  = o & 8191;
    int d  = r >> 6;
    int d2p = (r & 63) * 2;
    const float* src = Mp + (size_t)bh * (HD_ * HD_) + (size_t)d2p * HD_ + d;
    float s0 = 0.f, s1 = 0.f;
    const size_t stride = (size_t)32 * HD_ * HD_;
#pragma unroll
    for (int p = 0; p < KVSPLIT; p++) {
        s0 += src[p * stride];
        s1 += src[p * stride + HD_];
    }
    s0 *= 0.08838834764831845f;
    s1 *= 0.08838834764831845f;
    size_t off = (size_t)bh * (HD_ * HD_) + (size_t)d * HD_ + d2p;
    *(__half2*)(mt + off) = __floats2half2_rn(s0, s1);
}

// ---------------- fp32 -> fp16 hi/lo split ---------------------------------
__global__ void split_fp32_fp16(const float* __restrict__ x,
                                __half* __restrict__ hi,
                                __half* __restrict__ lo, int n)
{
    int i = (blockIdx.x * 256 + threadIdx.x) * 4;
    if (i >= n) return;
    float4 v = *(const float4*)(x + i);
    __half2 h01, l01, h23, l23;
    split2h(v.x, v.y, h01, l01);
    split2h(v.z, v.w, h23, l23);
    ((__half2*)(hi + i))[0] = h01;
    ((__half2*)(hi + i))[1] = h23;
    ((__half2*)(lo + i))[0] = l01;
    ((__half2*)(lo + i))[1] = l23;
}

// ---------------- fused 4-weight fp32 -> fp16 round ------------------------
__global__ void round_w4(const float* __restrict__ w0, const float* __restrict__ w1,
                         const float* __restrict__ w2, const float* __restrict__ w3,
                         __half* __restrict__ o)
{
    int t = (blockIdx.x * 256 + threadIdx.x) * 4;
    int seg = t >> 22;                 // NW_ = 2^22
    int off = t & (NW_ - 1);
    const float* src = (seg == 0) ? w0 : (seg == 1) ? w1 : (seg == 2) ? w2 : w3;
    float4 v = *(const float4*)(src + off);
    ((__half2*)(o + t))[0] = __floats2half2_rn(v.x, v.y);
    ((__half2*)(o + t))[1] = __floats2half2_rn(v.z, v.w);
}

// ---------------------------------------------------------------------------
extern "C" void kernel_launch(void* const* d_in, const int* in_sizes, int n_in,
                              void* d_out, int out_size)
{
    const float* x  = (const float*)d_in[0];
    const float* fc = (const float*)d_in[1];
    const float* fs = (const float*)d_in[2];
    const float* wq = (const float*)d_in[3];
    const float* bq = (const float*)d_in[4];
    const float* wk = (const float*)d_in[5];
    const float* bk = (const float*)d_in[6];
    const float* wv = (const float*)d_in[7];
    const float* bv = (const float*)d_in[8];
    const float* wo = (const float*)d_in[9];
    const float* bo = (const float*)d_in[10];
    float* out = (float*)d_out;

    float *pQ, *pK, *pV, *pMp;
    __half *pxh, *pxl, *pw, *pah, *pal;
    __half *pqh, *pql, *pkth, *pktl, *pvt, *pmt;
    cudaGetSymbolAddress((void**)&pQ,  g_Q);
    cudaGetSymbolAddress((void**)&pK,  g_K);
    cudaGetSymbolAddress((void**)&pV,  g_V);
    cudaGetSymbolAddress((void**)&pMp, g_Mp);
    cudaGetSymbolAddress((void**)&pxh, g_xhi);
    cudaGetSymbolAddress((void**)&pxl, g_xlo);
    cudaGetSymbolAddress((void**)&pw,  g_w);
    cudaGetSymbolAddress((void**)&pah, g_ahi);
    cudaGetSymbolAddress((void**)&pal, g_alo);
    cudaGetSymbolAddress((void**)&pqh, g_qhi);
    cudaGetSymbolAddress((void**)&pql, g_qlo);
    cudaGetSymbolAddress((void**)&pkth, g_kthi);
    cudaGetSymbolAddress((void**)&pktl, g_ktlo);
    cudaGetSymbolAddress((void**)&pvt, g_vt);
    cudaGetSymbolAddress((void**)&pmt, g_mt);

    cudaFuncSetAttribute(gemm_qkv,  cudaFuncAttributeMaxDynamicSharedMemorySize, GEMM2_SMEM);
    cudaFuncSetAttribute(gemm_wo,   cudaFuncAttributeMaxDynamicSharedMemorySize, GEMM2_SMEM);
    cudaFuncSetAttribute(kv_hmma,   cudaFuncAttributeMaxDynamicSharedMemorySize, GEMM2_SMEM);
    cudaFuncSetAttribute(attn_hmma, cudaFuncAttributeMaxDynamicSharedMemorySize, GEMM2_SMEM);
    cudaFuncSetAttribute(prep_qkv,  cudaFuncAttributeMaxDynamicSharedMemorySize, PREP_SMEM);

    dim3 blk(256);
    const int NX = MROWS * DIM_;
    const size_t WSTRIDE = (size_t)NW_;

    split_fp32_fp16<<<NX / 1024, blk>>>(x, pxh, pxl, NX);
    round_w4<<<4 * NW_ / 1024, blk>>>(wq, wk, wv, wo, pw);

    gemm_qkv<<<dim3(48, 32), blk, GEMM2_SMEM>>>(pxh, pxl, pw,
                                                bq, bk, bv, pQ, pK, pV);

    prep_qkv<<<dim3(16, 32), blk, PREP_SMEM>>>(pQ, pK, pV, fc, fs,
                                               pqh, pql, pkth, pktl, pvt);

    kv_hmma<<<dim3(KVSPLIT, 32), blk, GEMM2_SMEM>>>(pkth, pktl, pvt, pMp);

    reduce_mt<<<(32 * HD_ * HD_ / 2) / 256, blk>>>(pMp, pmt);

    attn_hmma<<<dim3(16, 32), blk, GEMM2_SMEM>>>(pqh, pql, pmt, pah, pal);

    gemm_wo<<<dim3(16, 32), blk, GEMM2_SMEM>>>(pah, pal, pw + 3 * WSTRIDE,
                                               bo, out);
}

// round 10
// speedup vs baseline: 4.7323x; 1.0201x over previous
#include <cuda_runtime.h>
#include <cuda_fp16.h>
#include <cstdint>

#define B_  2
#define S_  2048
#define DIM_ 2048
#define NH_ 16
#define HD_ 128
#define MROWS (B_*S_)          // 4096
#define KVSPLIT 8
#define NW_ (DIM_*DIM_)        // 4194304 = 2^22

// ---------------- scratch (device globals; no allocation) ----------------
__device__ __align__(16) float g_Mp[(size_t)KVSPLIT * B_ * NH_ * HD_ * HD_];

__device__ __align__(16) __half g_xhi[(size_t)MROWS * DIM_];
__device__ __align__(16) __half g_xlo[(size_t)MROWS * DIM_];
__device__ __align__(16) __half g_w[4][(size_t)NW_];
__device__ __align__(16) __half g_ahi[(size_t)MROWS * DIM_];
__device__ __align__(16) __half g_alo[(size_t)MROWS * DIM_];

__device__ __align__(16) __half g_qhi[(size_t)MROWS * DIM_];
__device__ __align__(16) __half g_qlo[(size_t)MROWS * DIM_];
__device__ __align__(16) __half g_kthi[(size_t)B_ * NH_ * HD_ * S_];
__device__ __align__(16) __half g_ktlo[(size_t)B_ * NH_ * HD_ * S_];
__device__ __align__(16) __half g_vt [(size_t)B_ * NH_ * HD_ * S_];
__device__ __align__(16) __half g_mt [(size_t)B_ * NH_ * HD_ * HD_];

// ======================= PTX helpers ==========================
__device__ __forceinline__ uint32_t smem_u32(const void* p) {
    uint32_t a;
    asm("{ .reg .u64 t; cvta.to.shared.u64 t, %1; cvt.u32.u64 %0, t; }"
        : "=r"(a) : "l"(p));
    return a;
}

__device__ __forceinline__ void ldsm_x4(uint32_t* r, uint32_t addr) {
    asm volatile("ldmatrix.sync.aligned.m8n8.x4.shared.b16 {%0,%1,%2,%3}, [%4];"
                 : "=r"(r[0]), "=r"(r[1]), "=r"(r[2]), "=r"(r[3]) : "r"(addr));
}

__device__ __forceinline__ void mma_f16(float* d, const uint32_t* a, const uint32_t* b) {
    asm volatile(
        "mma.sync.aligned.m16n8k16.row.col.f32.f16.f16.f32 "
        "{%0,%1,%2,%3}, {%4,%5,%6,%7}, {%8,%9}, {%0,%1,%2,%3};"
        : "+f"(d[0]), "+f"(d[1]), "+f"(d[2]), "+f"(d[3])
        : "r"(a[0]), "r"(a[1]), "r"(a[2]), "r"(a[3]), "r"(b[0]), "r"(b[1]));
}

#define CP_ASYNC16(dst, src) \
    asm volatile("cp.async.cg.shared.global [%0], [%1], 16;" :: "r"(dst), "l"(src))
#define CP_COMMIT() asm volatile("cp.async.commit_group;" ::: "memory")
#define CP_WAIT0()  asm volatile("cp.async.wait_group 0;" ::: "memory")
#define CP_WAIT1()  asm volatile("cp.async.wait_group 1;" ::: "memory")

#define SW128(bo) ((bo) ^ (((bo) >> 3) & 0x70))

__device__ __forceinline__ void split2h(float a, float b,
                                        __half2& hi, __half2& lo) {
    __half ha = __float2half(a), hb = __float2half(b);
    hi = __halves2half2(ha, hb);
    lo = __halves2half2(__float2half(a - __half2float(ha)),
                        __float2half(b - __half2float(hb)));
}

// ============ fp16 2-pass 128x128 mainloop =====================
// C = (Ahi + Alo) . B ; B pre-rounded to fp16.
#define STAGE2_BYTES 49152
#define GEMM2_SMEM   (2 * STAGE2_BYTES)

__device__ __forceinline__ void mm_tile2(
    const __half* Ahi, const __half* Alo, const __half* Bf,
    int lda, int ldb, int chunks, char* smem, float (&acc)[4][4][4])
{
    const uint32_t sbase = smem_u32(smem);
    const int tid  = threadIdx.x;
    const int lane = tid & 31;
    const int w    = tid >> 5;
    const int wm   = (w & 1) * 64;
    const int wn   = (w >> 1) * 32;

    const __half* gb[3] = {Ahi, Alo, Bf};
    const int lds[3] = {lda, lda, ldb};

    auto stage_load = [&](int buf, int kbase) {
        const uint32_t sp0 = sbase + buf * STAGE2_BYTES;
#pragma unroll
        for (int m = 0; m < 3; m++) {
            const __half* gp = gb[m] + kbase;
            const int ld = lds[m];
            const uint32_t sp = sp0 + m * 16384;
#pragma unroll
            for (int j = 0; j < 4; j++) {
                int id  = j * 256 + tid;
                int row = id >> 3;
                int ch  = id & 7;
                uint32_t bo = row * 128 + ch * 16;
                CP_ASYNC16(sp + SW128(bo), (const char*)(gp + (size_t)row * ld) + ch * 16);
            }
        }
    };

    stage_load(0, 0);
    CP_COMMIT();

    const int a_row  = lane & 15;
    const int a_koff = (lane >> 4) * 16;
    const int b_row  = (lane & 7) + ((lane >> 4) << 3);
    const int b_koff = ((lane >> 3) & 1) * 16;

    for (int c = 0; c < chunks; c++) {
        if (c + 1 < chunks) {
            stage_load((c + 1) & 1, (c + 1) * 64);
            CP_COMMIT();
            CP_WAIT1();
        } else {
            CP_WAIT0();
        }
        __syncthreads();

        const uint32_t sA_hi = sbase + (c & 1) * STAGE2_BYTES;
        const uint32_t sA_lo = sA_hi + 16384;
        const uint32_t sB    = sA_hi + 32768;

#pragma unroll
        for (int ks = 0; ks < 4; ks++) {
            const int kb2 = ks * 32;
            uint32_t ahi[4][4], alo[4][4], bf[2][4];
#pragma unroll
            for (int mt = 0; mt < 4; mt++) {
                uint32_t bo = (wm + mt * 16 + a_row) * 128 + kb2 + a_koff;
                uint32_t sw = SW128(bo);
                ldsm_x4(ahi[mt], sA_hi + sw);
                ldsm_x4(alo[mt], sA_lo + sw);
            }
#pragma unroll
            for (int bt = 0; bt < 2; bt++) {
                uint32_t bo = (wn + bt * 16 + b_row) * 128 + kb2 + b_koff;
                uint32_t sw = SW128(bo);
                ldsm_x4(bf[bt], sB + sw);
            }
#pragma unroll
            for (int mt = 0; mt < 4; mt++) {
#pragma unroll
                for (int nt = 0; nt < 4; nt++) {
                    const uint32_t* bp = &bf[nt >> 1][(nt & 1) * 2];
                    mma_f16(acc[mt][nt], ahi[mt], bp);
                    mma_f16(acc[mt][nt], alo[mt], bp);
                }
            }
        }
        __syncthreads();
    }
}

#define ACC_INIT(acc) \
    _Pragma("unroll") for (int i = 0; i < 4; i++) \
    _Pragma("unroll") for (int j = 0; j < 4; j++) \
    _Pragma("unroll") for (int q = 0; q < 4; q++) acc[i][j][q] = 0.f;

// ============ fused QKV GEMM + rope/split/transpose epilogue ===============
// grid (48, 32). Column tile == one head (HD==128).
//   wsel 0 (Q): bias+rope+split -> qhi/qlo row-major
//   wsel 1 (K): bias+rope+split -> transpose -> kthi/ktlo [bh][d][s]
//   wsel 2 (V): bias+round      -> transpose -> vt        [bh][d][s]
__global__ void __launch_bounds__(256, 2)
gemm_qkv(const __half* __restrict__ xhi, const __half* __restrict__ xlo,
         const __half* __restrict__ wf,
         const float* __restrict__ bq, const float* __restrict__ bk,
         const float* __restrict__ bv,
         const float* __restrict__ fc, const float* __restrict__ fs,
         __half* __restrict__ qhi, __half* __restrict__ qlo,
         __half* __restrict__ kthi, __half* __restrict__ ktlo,
         __half* __restrict__ vt)
{
    extern __shared__ char smem[];
    const int bx = blockIdx.x, by = blockIdx.y;
    const int wsel = bx >> 4;
    const int col0 = (bx & 15) * 128;
    const int row0 = by * 128;

    float acc[4][4][4];
    ACC_INIT(acc)
    mm_tile2(xhi + (size_t)row0 * DIM_, xlo + (size_t)row0 * DIM_,
             wf + (size_t)bx * 128 * DIM_,
             DIM_, DIM_, DIM_ / 64, smem, acc);

    const int tid  = threadIdx.x;
    const int lane = tid & 31, w = tid >> 5;
    const int wm = (w & 1) * 64, wn = (w >> 1) * 32;
    const int l4 = lane >> 2, l2 = (lane & 3) * 2;

    const int s0 = (by & 15) * 128;   // s offset within batch
    const int b  = by >> 4;
    const int h  = bx & 15;

    if (wsel == 0) {
        // ---- Q: bias + rope + split, row-major ----
#pragma unroll
        for (int mt = 0; mt < 4; mt++) {
#pragma unroll
            for (int nt = 0; nt < 4; nt++) {
                const int cl = wn + nt * 8 + l2;        // even, within-head dim
                const int i  = cl >> 1;
                const float b0 = __ldg(bq + col0 + cl);
                const float b1 = __ldg(bq + col0 + cl + 1);
#pragma unroll
                for (int rr = 0; rr < 2; rr++) {
                    const int sl = wm + mt * 16 + l4 + rr * 8;
                    const int sg = s0 + sl;
                    const float c  = __ldg(fc + sg * 64 + i);
                    const float sn = __ldg(fs + sg * 64 + i);
                    const float v0 = acc[mt][nt][rr * 2 + 0] + b0;
                    const float v1 = acc[mt][nt][rr * 2 + 1] + b1;
                    const float o0 = v0 * c - v1 * sn;
                    const float o1 = v0 * sn + v1 * c;
                    __half2 hi, lo;
                    split2h(o0, o1, hi, lo);
                    const size_t off = (size_t)(row0 + sl) * DIM_ + col0 + cl;
                    *(__half2*)(qhi + off) = hi;
                    *(__half2*)(qlo + off) = lo;
                }
            }
        }
    } else {
        // ---- K / V: into transposed smem buffers ----
        __half* sh_hi = (__half*)smem;
        __half* sh_lo = sh_hi + 128 * 136;
        const float* bias = (wsel == 1) ? bk : bv;
#pragma unroll
        for (int mt = 0; mt < 4; mt++) {
#pragma unroll
            for (int nt = 0; nt < 4; nt++) {
                const int cl = wn + nt * 8 + l2;
                const float b0 = __ldg(bias + col0 + cl);
                const float b1 = __ldg(bias + col0 + cl + 1);
#pragma unroll
                for (int rr = 0; rr < 2; rr++) {
                    const int sl = wm + mt * 16 + l4 + rr * 8;
                    const float v0 = acc[mt][nt][rr * 2 + 0] + b0;
                    const float v1 = acc[mt][nt][rr * 2 + 1] + b1;
                    if (wsel == 1) {
                        const int i  = cl >> 1;
                        const int sg = s0 + sl;
                        const float c  = __ldg(fc + sg * 64 + i);
                        const float sn = __ldg(fs + sg * 64 + i);
                        const float o0 = v0 * c - v1 * sn;
                        const float o1 = v0 * sn + v1 * c;
                        __half2 hi, lo;
                        split2h(o0, o1, hi, lo);
                        sh_hi[cl * 136 + sl]       = __low2half(hi);
                        sh_hi[(cl + 1) * 136 + sl] = __high2half(hi);
                        sh_lo[cl * 136 + sl]       = __low2half(lo);
                        sh_lo[(cl + 1) * 136 + sl] = __high2half(lo);
                    } else {
                        sh_hi[cl * 136 + sl]       = __float2half(v0);
                        sh_hi[(cl + 1) * 136 + sl] = __float2half(v1);
                    }
                }
            }
        }
        __syncthreads();
        const size_t tb = ((size_t)(b * NH_ + h)) * HD_ * S_ + s0;
        const int d  = tid >> 1;
        const int sc = (tid & 1) * 64;
        if (wsel == 1) {
#pragma unroll
            for (int j = 0; j < 8; j++) {
                const size_t go = tb + (size_t)d * S_ + sc + j * 8;
                *(uint4*)(kthi + go) = *(const uint4*)&sh_hi[d * 136 + sc + j * 8];
                *(uint4*)(ktlo + go) = *(const uint4*)&sh_lo[d * 136 + sc + j * 8];
            }
        } else {
#pragma unroll
            for (int j = 0; j < 8; j++) {
                const size_t go = tb + (size_t)d * S_ + sc + j * 8;
                *(uint4*)(vt + go) = *(const uint4*)&sh_hi[d * 136 + sc + j * 8];
            }
        }
    }
}

// ============ WO GEMM: grid (16, 32) =======================================
__global__ void __launch_bounds__(256, 2)
gemm_wo(const __half* __restrict__ Ahi, const __half* __restrict__ Alo,
        const __half* __restrict__ Bf,
        const float* __restrict__ bias, float* __restrict__ C)
{
    extern __shared__ char smem[];
    const int row0 = blockIdx.y * 128;
    const int col0 = blockIdx.x * 128;

    float acc[4][4][4];
    ACC_INIT(acc)
    mm_tile2(Ahi + (size_t)row0 * DIM_, Alo + (size_t)row0 * DIM_,
             Bf + (size_t)col0 * DIM_,
             DIM_, DIM_, DIM_ / 64, smem, acc);

    const int lane = threadIdx.x & 31, w = threadIdx.x >> 5;
    const int wm = (w & 1) * 64, wn = (w >> 1) * 32;
    const int l4 = lane >> 2, l2 = (lane & 3) * 2;
#pragma unroll
    for (int mt = 0; mt < 4; mt++) {
#pragma unroll
        for (int nt = 0; nt < 4; nt++) {
            int grow = row0 + wm + mt * 16 + l4;
            int gcol = col0 + wn + nt * 8 + l2;
            float b0 = __ldg(bias + gcol);
            float b1 = __ldg(bias + gcol + 1);
            float* cp0 = C + (size_t)grow * DIM_ + gcol;
            float* cp1 = cp0 + 8 * (size_t)DIM_;
            *(float2*)cp0 = make_float2(acc[mt][nt][0] + b0, acc[mt][nt][1] + b1);
            *(float2*)cp1 = make_float2(acc[mt][nt][2] + b0, acc[mt][nt][3] + b1);
        }
    }
}

// ============ KtV GEMM (fp16 2-pass): grid (KVSPLIT, 32) ===================
__global__ void __launch_bounds__(256, 2)
kv_hmma(const __half* __restrict__ kthi, const __half* __restrict__ ktlo,
        const __half* __restrict__ vt, float* __restrict__ Mp)
{
    extern __shared__ char smem[];
    const int ksp = blockIdx.x;
    const int bh  = blockIdx.y;
    const size_t base = (size_t)bh * HD_ * S_ + ksp * (S_ / KVSPLIT);

    float acc[4][4][4];
    ACC_INIT(acc)
    mm_tile2(kthi + base, ktlo + base, vt + base,
             S_, S_, (S_ / KVSPLIT) / 64, smem, acc);

    float* C = Mp + ((size_t)ksp * 32 + bh) * (HD_ * HD_);
    const int lane = threadIdx.x & 31, w = threadIdx.x >> 5;
    const int wm = (w & 1) * 64, wn = (w >> 1) * 32;
    const int l4 = lane >> 2, l2 = (lane & 3) * 2;
#pragma unroll
    for (int mt = 0; mt < 4; mt++) {
#pragma unroll
        for (int nt = 0; nt < 4; nt++) {
            int grow = wm + mt * 16 + l4;
            int gcol = wn + nt * 8 + l2;
            float* cp0 = C + (size_t)grow * HD_ + gcol;
            float* cp1 = cp0 + 8 * HD_;
            *(float2*)cp0 = make_float2(acc[mt][nt][0], acc[mt][nt][1]);
            *(float2*)cp1 = make_float2(acc[mt][nt][2], acc[mt][nt][3]);
        }
    }
}

// ============ attn GEMM (fp16 2-pass): grid (16,32) ========================
__global__ void __launch_bounds__(256, 2)
attn_hmma(const __half* __restrict__ qhi, const __half* __restrict__ qlo,
          const __half* __restrict__ mt_,
          __half* __restrict__ ahi, __half* __restrict__ alo)
{
    extern __shared__ char smem[];
    const int st = blockIdx.x;
    const int bh = blockIdx.y;
    const int b = bh >> 4, h = bh & 15;
    const size_t abase = ((size_t)(b * S_ + st * 128)) * DIM_ + h * HD_;
    const size_t mbase = (size_t)bh * HD_ * HD_;

    float acc[4][4][4];
    ACC_INIT(acc)
    mm_tile2(qhi + abase, qlo + abase, mt_ + mbase,
             DIM_, HD_, HD_ / 64, smem, acc);

    const int lane = threadIdx.x & 31, w = threadIdx.x >> 5;
    const int wm = (w & 1) * 64, wn = (w >> 1) * 32;
    const int l4 = lane >> 2, l2 = (lane & 3) * 2;
#pragma unroll
    for (int mt = 0; mt < 4; mt++) {
#pragma unroll
        for (int nt = 0; nt < 4; nt++) {
            size_t off0 = abase + (size_t)(wm + mt * 16 + l4) * DIM_ + wn + nt * 8 + l2;
            size_t off1 = off0 + 8 * (size_t)DIM_;
            __half2 hi, lo;
            split2h(acc[mt][nt][0], acc[mt][nt][1], hi, lo);
            *(__half2*)(ahi + off0) = hi;
            *(__half2*)(alo + off0) = lo;
            split2h(acc[mt][nt][2], acc[mt][nt][3], hi, lo);
            *(__half2*)(ahi + off1) = hi;
            *(__half2*)(alo + off1) = lo;
        }
    }
}

// ============ reduce Mp over splits, scale, transpose, round ===============
__global__ void reduce_mt(const float* __restrict__ Mp, __half* __restrict__ mt)
{
    int o = blockIdx.x * 256 + threadIdx.x;
    int bh = o >> 13;
    int r  = o & 8191;
    int d  = r >> 6;
    int d2p = (r & 63) * 2;
    const float* src = Mp + (size_t)bh * (HD_ * HD_) + (size_t)d2p * HD_ + d;
    float s0 = 0.f, s1 = 0.f;
    const size_t stride = (size_t)32 * HD_ * HD_;
#pragma unroll
    for (int p = 0; p < KVSPLIT; p++) {
        s0 += src[p * stride];
        s1 += src[p * stride + HD_];
    }
    s0 *= 0.08838834764831845f;
    s1 *= 0.08838834764831845f;
    size_t off = (size_t)bh * (HD_ * HD_) + (size_t)d * HD_ + d2p;
    *(__half2*)(mt + off) = __floats2half2_rn(s0, s1);
}

// ---------------- fp32 -> fp16 hi/lo split ---------------------------------
__global__ void split_fp32_fp16(const float* __restrict__ x,
                                __half* __restrict__ hi,
                                __half* __restrict__ lo, int n)
{
    int i = (blockIdx.x * 256 + threadIdx.x) * 4;
    if (i >= n) return;
    float4 v = *(const float4*)(x + i);
    __half2 h01, l01, h23, l23;
    split2h(v.x, v.y, h01, l01);
    split2h(v.z, v.w, h23, l23);
    ((__half2*)(hi + i))[0] = h01;
    ((__half2*)(hi + i))[1] = h23;
    ((__half2*)(lo + i))[0] = l01;
    ((__half2*)(lo + i))[1] = l23;
}

// ---------------- fused 4-weight fp32 -> fp16 round ------------------------
__global__ void round_w4(const float* __restrict__ w0, const float* __restrict__ w1,
                         const float* __restrict__ w2, const float* __restrict__ w3,
                         __half* __restrict__ o)
{
    int t = (blockIdx.x * 256 + threadIdx.x) * 4;
    int seg = t >> 22;                 // NW_ = 2^22
    int off = t & (NW_ - 1);
    const float* src = (seg == 0) ? w0 : (seg == 1) ? w1 : (seg == 2) ? w2 : w3;
    float4 v = *(const float4*)(src + off);
    ((__half2*)(o + t))[0] = __floats2half2_rn(v.x, v.y);
    ((__half2*)(o + t))[1] = __floats2half2_rn(v.z, v.w);
}

// ---------------------------------------------------------------------------
extern "C" void kernel_launch(void* const* d_in, const int* in_sizes, int n_in,
                              void* d_out, int out_size)
{
    const float* x  = (const float*)d_in[0];
    const float* fc = (const float*)d_in[1];
    const float* fs = (const float*)d_in[2];
    const float* wq = (const float*)d_in[3];
    const float* bq = (const float*)d_in[4];
    const float* wk = (const float*)d_in[5];
    const float* bk = (const float*)d_in[6];
    const float* wv = (const float*)d_in[7];
    const float* bv = (const float*)d_in[8];
    const float* wo = (const float*)d_in[9];
    const float* bo = (const float*)d_in[10];
    float* out = (float*)d_out;

    float *pMp;
    __half *pxh, *pxl, *pw, *pah, *pal;
    __half *pqh, *pql, *pkth, *pktl, *pvt, *pmt;
    cudaGetSymbolAddress((void**)&pMp, g_Mp);
    cudaGetSymbolAddress((void**)&pxh, g_xhi);
    cudaGetSymbolAddress((void**)&pxl, g_xlo);
    cudaGetSymbolAddress((void**)&pw,  g_w);
    cudaGetSymbolAddress((void**)&pah, g_ahi);
    cudaGetSymbolAddress((void**)&pal, g_alo);
    cudaGetSymbolAddress((void**)&pqh, g_qhi);
    cudaGetSymbolAddress((void**)&pql, g_qlo);
    cudaGetSymbolAddress((void**)&pkth, g_kthi);
    cudaGetSymbolAddress((void**)&pktl, g_ktlo);
    cudaGetSymbolAddress((void**)&pvt, g_vt);
    cudaGetSymbolAddress((void**)&pmt, g_mt);

    cudaFuncSetAttribute(gemm_qkv,  cudaFuncAttributeMaxDynamicSharedMemorySize, GEMM2_SMEM);
    cudaFuncSetAttribute(gemm_wo,   cudaFuncAttributeMaxDynamicSharedMemorySize, GEMM2_SMEM);
    cudaFuncSetAttribute(kv_hmma,   cudaFuncAttributeMaxDynamicSharedMemorySize, GEMM2_SMEM);
    cudaFuncSetAttribute(attn_hmma, cudaFuncAttributeMaxDynamicSharedMemorySize, GEMM2_SMEM);

    dim3 blk(256);
    const int NX = MROWS * DIM_;
    const size_t WSTRIDE = (size_t)NW_;

    split_fp32_fp16<<<NX / 1024, blk>>>(x, pxh, pxl, NX);
    round_w4<<<4 * NW_ / 1024, blk>>>(wq, wk, wv, wo, pw);

    gemm_qkv<<<dim3(48, 32), blk, GEMM2_SMEM>>>(pxh, pxl, pw,
                                                bq, bk, bv, fc, fs,
                                                pqh, pql, pkth, pktl, pvt);

    kv_hmma<<<dim3(KVSPLIT, 32), blk, GEMM2_SMEM>>>(pkth, pktl, pvt, pMp);

    reduce_mt<<<(32 * HD_ * HD_ / 2) / 256, blk>>>(pMp, pmt);

    attn_hmma<<<dim3(16, 32), blk, GEMM2_SMEM>>>(pqh, pql, pmt, pah, pal);

    gemm_wo<<<dim3(16, 32), blk, GEMM2_SMEM>>>(pah, pal, pw + 3 * WSTRIDE,
                                               bo, out);
}